// round 12
// baseline (speedup 1.0000x reference)
#include <cuda_runtime.h>
#include <cuda_fp16.h>
#include <mma.h>
#include <cstdint>
#include <cfloat>

using namespace nvcuda;

#define B   64
#define H   1024
#define V   32000
#define T   40
#define G4  4096
#define SOS 1

#define KC   64
#define PE   72                     // smem pitch in half elements
#define ROWB 144                    // pitch bytes
#define NST  (H / KC)               // 16 stages (proj)
#define NPART (V / 128)             // 250 proj blocks

// ---- LSTM geometry (BM=64) ----
#define ARRB64 (64 * ROWB)          // 9216
#define STG64  (4 * ARRB64)         // 36864
#define DSMEM_L (2 * STG64)         // 73728

// ---- proj geometry (BM=128) ----
#define ARRB128 (128 * ROWB)        // 18432
#define STG128  (2 * ARRB128 + 2 * ARRB64)   // 55296
#define DSMEM_P (2 * STG128)        // 110592

// ---------------- persistent device state (device-code access ONLY) ----------
__device__ __align__(16) __half g_Wout_h[(size_t)V * H];
__device__ __align__(16) __half g_Wout_l[(size_t)V * H];
__device__ __align__(16) __half g_Wih_h[(size_t)G4 * H];
__device__ __align__(16) __half g_Wih_l[(size_t)G4 * H];
__device__ __align__(16) __half g_Whh_h[(size_t)G4 * H];
__device__ __align__(16) __half g_Whh_l[(size_t)G4 * H];
__device__ __align__(16) __half g_xh[B * H],  g_xl[B * H];
__device__ __align__(16) __half g_hh[B * H],  g_hl[B * H];
__device__ float g_c[B * H];
__device__ float g_gp0[64 * 64 * B];   // k-half 0 partial: [(mb*64+row)*64+n]
__device__ float g_gp1[64 * 64 * B];   // k-half 1 partial
__device__ int   g_cnt[64];            // per-mb arrival counter (self-resetting)
__device__ float g_pv[NPART * B];      // proj partial argmax values
__device__ int   g_pi[NPART * B];      // proj partial argmax indices

// ---------------- helpers ------------------------------------------------------
__device__ __forceinline__ uint32_t smem_u32(const void* p) {
    uint32_t a;
    asm("{ .reg .u64 t; cvta.to.shared.u64 t, %1; cvt.u32.u64 %0, t; }"
        : "=r"(a) : "l"(p));
    return a;
}
__device__ __forceinline__ void cp16(uint32_t s, const void* g) {
    asm volatile("cp.async.cg.shared.global [%0], [%1], 16;" :: "r"(s), "l"(g));
}
__device__ __forceinline__ void cp_commit() {
    asm volatile("cp.async.commit_group;" ::: "memory");
}
__device__ __forceinline__ void cp_wait1() {
    asm volatile("cp.async.wait_group 1;" ::: "memory");
}
__device__ __forceinline__ void cp_wait0() {
    asm volatile("cp.async.wait_group 0;" ::: "memory");
}
__device__ __forceinline__ void split_pair(float x, __half& hi, __half& lo) {
    hi = __float2half_rn(x);
    lo = __float2half_rn(x - __half2float(hi));
}

// ---------------- fused LSTM kernel --------------------------------------------
// Grid 128: block = (kh = bid>>6, mb = bid&63).
// Block (kh, mb) computes, over k in [kh*512, kh*512+512) of BOTH terms
// (w_ih*x + w_hh*h), the 64 gate rows {g*1024 + mb*16 + u}.  Partials land in
// g_gp{kh}; the second block to finish per mb applies biases + LSTM activation
// for hidden units [mb*16, mb*16+16) and updates g_c / g_hh / g_hl.
__global__ __launch_bounds__(256, 2)
void lstm_fused(const float* __restrict__ b_ih, const float* __restrict__ b_hh)
{
    extern __shared__ char sm[];
    float* sC   = reinterpret_cast<float*>(sm);
    __half* sCh = reinterpret_cast<__half*>(sm + 64 * 68 * 4);

    const int tid = threadIdx.x;
    const int wid = tid >> 5;
    const int ms = (wid & 3) * 16;
    const int nb = (wid >> 2) * 32;
    const int kh = blockIdx.x >> 6;
    const int mb = blockIdx.x & 63;
    const int kbase = kh * 512;
    const uint32_t sbase = smem_u32(sm);

    // loader rows
    const int r0 = tid >> 3,         c0 = tid & 7;
    const int r1 = r0 + 32;
    const uint32_t so0 = (uint32_t)(r0 * ROWB + c0 * 16);
    const uint32_t so1 = (uint32_t)(r1 * ROWB + c0 * 16);
    // gate-gathered global rows for A
    const size_t grow0 = (size_t)((r0 >> 4) * 1024 + mb * 16 + (r0 & 15)) * H;
    const size_t grow1 = (size_t)((r1 >> 4) * 1024 + mb * 16 + (r1 & 15)) * H;

    wmma::fragment<wmma::accumulator, 16, 16, 16, float> fC[2];
    wmma::fragment<wmma::accumulator, 16, 16, 16, __half> fE[2];
    wmma::fill_fragment(fC[0], 0.0f);
    wmma::fill_fragment(fC[1], 0.0f);
    wmma::fill_fragment(fE[0], __float2half(0.0f));
    wmma::fill_fragment(fE[1], __float2half(0.0f));

    // chunk ch in [0,16): term = ch>>3 (0: w_ih*x, 1: w_hh*h), kc = ch&7
    auto load_chunk = [&](int ch, uint32_t sb) {
        const int term = ch >> 3;
        const int k = kbase + (ch & 7) * KC;
        const __half* Ahp = term ? g_Whh_h : g_Wih_h;
        const __half* Alp = term ? g_Whh_l : g_Wih_l;
        const __half* Bhp = term ? g_hh : g_xh;
        const __half* Blp = term ? g_hl : g_xl;
        const size_t oa0 = grow0 + k + c0 * 8;
        const size_t oa1 = grow1 + k + c0 * 8;
        const size_t ob0 = (size_t)r0 * H + k + c0 * 8;
        const size_t ob1 = (size_t)r1 * H + k + c0 * 8;
        cp16(sb + 0 * ARRB64 + so0, Ahp + oa0);  cp16(sb + 0 * ARRB64 + so1, Ahp + oa1);
        cp16(sb + 1 * ARRB64 + so0, Alp + oa0);  cp16(sb + 1 * ARRB64 + so1, Alp + oa1);
        cp16(sb + 2 * ARRB64 + so0, Bhp + ob0);  cp16(sb + 2 * ARRB64 + so1, Bhp + ob1);
        cp16(sb + 3 * ARRB64 + so0, Blp + ob0);  cp16(sb + 3 * ARRB64 + so1, Blp + ob1);
    };

    load_chunk(0, sbase);
    cp_commit();
    load_chunk(1, sbase + STG64);
    cp_commit();

    for (int s = 0; s < 16; s++) {
        if (s < 15) cp_wait1(); else cp_wait0();
        __syncthreads();

        const __half* st =
            reinterpret_cast<const __half*>(sm + (size_t)(s & 1) * STG64);
        const __half* sAh = st;
        const __half* sAl = st + ARRB64 / 2;
        const __half* sBh = st + 2 * (ARRB64 / 2);
        const __half* sBl = st + 3 * (ARRB64 / 2);

#pragma unroll
        for (int ks = 0; ks < KC; ks += 16) {
            wmma::fragment<wmma::matrix_a, 16, 16, 16, __half,
                           wmma::row_major> fAh, fAl;
            wmma::load_matrix_sync(fAh, sAh + ms * PE + ks, PE);
            wmma::load_matrix_sync(fAl, sAl + ms * PE + ks, PE);
#pragma unroll
            for (int j = 0; j < 2; j++) {
                wmma::fragment<wmma::matrix_b, 16, 16, 16, __half,
                               wmma::col_major> fBh, fBl;
                const int nr = nb + j * 16;
                wmma::load_matrix_sync(fBh, sBh + nr * PE + ks, PE);
                wmma::load_matrix_sync(fBl, sBl + nr * PE + ks, PE);
                wmma::mma_sync(fC[j], fAh, fBh, fC[j]);
                wmma::mma_sync(fE[j], fAh, fBl, fE[j]);
                wmma::mma_sync(fE[j], fAl, fBh, fE[j]);
            }
        }
        __syncthreads();

        if (s + 2 < 16) {
            load_chunk(s + 2, sbase + (uint32_t)(s & 1) * STG64);
        }
        cp_commit();
    }

    wmma::store_matrix_sync(sC + ms * 68 + nb,       fC[0], 68, wmma::mem_row_major);
    wmma::store_matrix_sync(sC + ms * 68 + nb + 16,  fC[1], 68, wmma::mem_row_major);
    wmma::store_matrix_sync(sCh + ms * 72 + nb,      fE[0], 72, wmma::mem_row_major);
    wmma::store_matrix_sync(sCh + ms * 72 + nb + 16, fE[1], 72, wmma::mem_row_major);
    __syncthreads();

    // write this k-half's partial
    float* gp = kh ? g_gp1 : g_gp0;
    const int ml = tid & 63;
    const int nlb = tid >> 6;
    const size_t pbase = (size_t)(mb * 64 + ml) * 64;
#pragma unroll
    for (int r = 0; r < 16; r++) {
        const int n = nlb + r * 4;
        gp[pbase + n] = sC[ml * 68 + n] + __half2float(sCh[ml * 72 + n]);
    }
    __syncthreads();

    // arrival: second finisher does the activation for this mb
    __shared__ int s_old;
    if (tid == 0) {
        __threadfence();
        s_old = atomicAdd(&g_cnt[mb], 1);
    }
    __syncthreads();
    if (s_old == 1) {
        __threadfence();
        const size_t mbb = (size_t)mb * 64 * 64;
        for (int e = tid; e < 1024; e += 256) {
            const int unit = e >> 6;
            const int n = e & 63;
            const int j = mb * 16 + unit;          // hidden index
            const size_t pi = mbb + (size_t)(0 * 16 + unit) * 64 + n;
            const size_t pf = mbb + (size_t)(1 * 16 + unit) * 64 + n;
            const size_t pg = mbb + (size_t)(2 * 16 + unit) * 64 + n;
            const size_t po = mbb + (size_t)(3 * 16 + unit) * 64 + n;
            float gi = g_gp0[pi] + g_gp1[pi] + b_ih[j]        + b_hh[j];
            float gf = g_gp0[pf] + g_gp1[pf] + b_ih[j + 1024] + b_hh[j + 1024];
            float gg = g_gp0[pg] + g_gp1[pg] + b_ih[j + 2048] + b_hh[j + 2048];
            float go = g_gp0[po] + g_gp1[po] + b_ih[j + 3072] + b_hh[j + 3072];
            const int idx = n * H + j;
            float c = g_c[idx];
            float si = 1.0f / (1.0f + expf(-gi));
            float sf = 1.0f / (1.0f + expf(-gf));
            float so = 1.0f / (1.0f + expf(-go));
            float c2 = sf * c + si * tanhf(gg);
            float h2 = so * tanhf(c2);
            g_c[idx] = c2;
            __half hi, lo;
            split_pair(h2, hi, lo);
            g_hh[idx] = hi;
            g_hl[idx] = lo;
        }
        __syncthreads();
        if (tid == 0) g_cnt[mb] = 0;   // reset for next step / next replay
    }
}

// ---------------- proj GEMM mainloop (BM=128) ----------------------------------
__device__ __forceinline__ void gemm128(
    const __half* __restrict__ Ah, const __half* __restrict__ Al,
    const __half* __restrict__ Bh, const __half* __restrict__ Bl,
    int m0, char* sm, float* sC, __half* sCh)
{
    const int tid = threadIdx.x;
    const int wid = tid >> 5;
    const int ms = (wid & 3) * 32;
    const int nb = (wid >> 2) * 32;
    const uint32_t sbase = smem_u32(sm);

    const int c0 = tid & 7;
    const uint32_t soA[4] = {
        (uint32_t)(((tid + 0)   >> 3) * ROWB + c0 * 16),
        (uint32_t)(((tid + 256) >> 3) * ROWB + c0 * 16),
        (uint32_t)(((tid + 512) >> 3) * ROWB + c0 * 16),
        (uint32_t)(((tid + 768) >> 3) * ROWB + c0 * 16)
    };
    const int rA[4] = { (tid + 0) >> 3, (tid + 256) >> 3,
                        (tid + 512) >> 3, (tid + 768) >> 3 };

    wmma::fragment<wmma::accumulator, 16, 16, 16, float> fC[2][2];
    wmma::fragment<wmma::accumulator, 16, 16, 16, __half> fE[2][2];
#pragma unroll
    for (int i = 0; i < 2; i++)
#pragma unroll
        for (int j = 0; j < 2; j++) {
            wmma::fill_fragment(fC[i][j], 0.0f);
            wmma::fill_fragment(fE[i][j], __float2half(0.0f));
        }

#pragma unroll
    for (int s = 0; s < 2; s++) {
        const int kt = s * KC;
        const uint32_t sb = sbase + (uint32_t)s * STG128;
#pragma unroll
        for (int v = 0; v < 4; v++) {
            const size_t ga = (size_t)(m0 + rA[v]) * H + kt + c0 * 8;
            cp16(sb + 0 * ARRB128 + soA[v], Ah + ga);
            cp16(sb + 1 * ARRB128 + soA[v], Al + ga);
        }
#pragma unroll
        for (int v = 0; v < 2; v++) {
            const size_t gb = (size_t)rA[v] * H + kt + c0 * 8;
            cp16(sb + 2 * ARRB128 + soA[v], Bh + gb);
            cp16(sb + 2 * ARRB128 + ARRB64 + soA[v], Bl + gb);
        }
        cp_commit();
    }

    for (int s = 0; s < NST; s++) {
        if (s < NST - 1) cp_wait1(); else cp_wait0();
        __syncthreads();

        const __half* st =
            reinterpret_cast<const __half*>(sm + (size_t)(s & 1) * STG128);
        const __half* sAh = st;
        const __half* sAl = st + ARRB128 / 2;
        const __half* sBh = st + 2 * (ARRB128 / 2);
        const __half* sBl = st + 2 * (ARRB128 / 2) + ARRB64 / 2;

#pragma unroll
        for (int ks = 0; ks < KC; ks += 16) {
            wmma::fragment<wmma::matrix_a, 16, 16, 16, __half,
                           wmma::row_major> fAh[2], fAl[2];
#pragma unroll
            for (int i = 0; i < 2; i++) {
                wmma::load_matrix_sync(fAh[i], sAh + (ms + i * 16) * PE + ks, PE);
                wmma::load_matrix_sync(fAl[i], sAl + (ms + i * 16) * PE + ks, PE);
            }
#pragma unroll
            for (int j = 0; j < 2; j++) {
                wmma::fragment<wmma::matrix_b, 16, 16, 16, __half,
                               wmma::col_major> fBh, fBl;
                const int nr = nb + j * 16;
                wmma::load_matrix_sync(fBh, sBh + nr * PE + ks, PE);
                wmma::load_matrix_sync(fBl, sBl + nr * PE + ks, PE);
#pragma unroll
                for (int i = 0; i < 2; i++) {
                    wmma::mma_sync(fC[i][j], fAh[i], fBh, fC[i][j]);
                    wmma::mma_sync(fE[i][j], fAh[i], fBl, fE[i][j]);
                    wmma::mma_sync(fE[i][j], fAl[i], fBh, fE[i][j]);
                }
            }
        }
        __syncthreads();

        if (s + 2 < NST) {
            const int kt = (s + 2) * KC;
            const uint32_t sb = sbase + (uint32_t)(s & 1) * STG128;
#pragma unroll
            for (int v = 0; v < 4; v++) {
                const size_t ga = (size_t)(m0 + rA[v]) * H + kt + c0 * 8;
                cp16(sb + 0 * ARRB128 + soA[v], Ah + ga);
                cp16(sb + 1 * ARRB128 + soA[v], Al + ga);
            }
#pragma unroll
            for (int v = 0; v < 2; v++) {
                const size_t gb = (size_t)rA[v] * H + kt + c0 * 8;
                cp16(sb + 2 * ARRB128 + soA[v], Bh + gb);
                cp16(sb + 2 * ARRB128 + ARRB64 + soA[v], Bl + gb);
            }
            cp_commit();
        }
    }

#pragma unroll
    for (int i = 0; i < 2; i++)
#pragma unroll
        for (int j = 0; j < 2; j++) {
            wmma::store_matrix_sync(sC + (ms + i * 16) * 68 + nb + j * 16,
                                    fC[i][j], 68, wmma::mem_row_major);
            wmma::store_matrix_sync(sCh + (ms + i * 16) * 72 + nb + j * 16,
                                    fE[i][j], 72, wmma::mem_row_major);
        }
    __syncthreads();
}

// ---------------- projection kernel (BM=128, occ 2) + partial argmax -----------
__global__ __launch_bounds__(256, 2)
void proj_tc(int useX0, float* __restrict__ dst, int t,
             const float* __restrict__ bias)
{
    extern __shared__ char sm[];
    float* sC  = reinterpret_cast<float*>(sm);
    __half* sCh = reinterpret_cast<__half*>(sm + 128 * 68 * 4);
    __shared__ float sBias[128];
    __shared__ float sPV[256];
    __shared__ int   sPI[256];

    const int tid = threadIdx.x;
    const int m0 = blockIdx.x * 128;
    if (tid < 128) sBias[tid] = bias[m0 + tid];

    const __half* Bh = useX0 ? g_xh : g_hh;
    const __half* Bl = useX0 ? g_xl : g_hl;
    gemm128(g_Wout_h, g_Wout_l, Bh, Bl, m0, sm, sC, sCh);

    const int ml = tid & 127;
    const int nlb = tid >> 7;
    const int gm = m0 + ml;
    const float bb = sBias[ml];
#pragma unroll
    for (int r = 0; r < 32; r++) {
        const int n = nlb + r * 2;
        dst[((size_t)n * T + t) * (size_t)V + gm] =
            sC[ml * 68 + n] + __half2float(sCh[ml * 72 + n]) + bb;
    }

    const int n = tid & 63, q = tid >> 6;
    float bv = -FLT_MAX;
    int bi = 0;
    for (int r = q * 32; r < q * 32 + 32; r++) {
        float v = sC[r * 68 + n] + __half2float(sCh[r * 72 + n]) + sBias[r];
        if (v > bv) { bv = v; bi = m0 + r; }
    }
    sPV[tid] = bv;
    sPI[tid] = bi;
    __syncthreads();
    if (tid < 64) {
        float v0 = sPV[tid];
        int   i0 = sPI[tid];
#pragma unroll
        for (int qq = 1; qq < 4; qq++) {
            float v = sPV[tid + qq * 64];
            int   i = sPI[tid + qq * 64];
            if (v > v0 || (v == v0 && i < i0)) { v0 = v; i0 = i; }
        }
        g_pv[blockIdx.x * B + tid] = v0;
        g_pi[blockIdx.x * B + tid] = i0;
    }
}

// ---------------- weight pre-split ---------------------------------------------
__global__ void split_weights(const float* __restrict__ src, int which, int n4) {
    int i4 = blockIdx.x * blockDim.x + threadIdx.x;
    if (i4 >= n4) return;
    __half* dh;
    __half* dl;
    if (which == 0)      { dh = g_Wout_h; dl = g_Wout_l; }
    else if (which == 1) { dh = g_Wih_h;  dl = g_Wih_l; }
    else                 { dh = g_Whh_h;  dl = g_Whh_l; }
    float4 v = reinterpret_cast<const float4*>(src)[i4];
    __half h0, l0, h1, l1, h2, l2, h3, l3;
    split_pair(v.x, h0, l0);
    split_pair(v.y, h1, l1);
    split_pair(v.z, h2, l2);
    split_pair(v.w, h3, l3);
    size_t o = (size_t)i4 * 4;
    dh[o] = h0; dh[o + 1] = h1; dh[o + 2] = h2; dh[o + 3] = h3;
    dl[o] = l0; dl[o + 1] = l1; dl[o + 2] = l2; dl[o + 3] = l3;
}

// ---------------- small kernels --------------------------------------------------
__global__ void init_kernel(const float* __restrict__ h0,
                            const float* __restrict__ c0,
                            const float* __restrict__ embed,
                            float* __restrict__ out, int mode) {
    int idx = blockIdx.x * blockDim.x + threadIdx.x;
    if (idx < B * H) {
        g_c[idx] = c0[idx];
        __half hi, lo;
        split_pair(h0[idx], hi, lo);
        g_hh[idx] = hi;
        g_hl[idx] = lo;
        split_pair(embed[(size_t)SOS * H + (idx & (H - 1))], hi, lo);
        g_xh[idx] = hi;
        g_xl[idx] = lo;
    }
    if (idx < 64) g_cnt[idx] = 0;
    if (idx < B && mode)
        out[(size_t)B * T * V + (size_t)idx * T + 0] = (float)SOS;
}

__global__ void fill_zero(float* __restrict__ p, int n) {
    int i = blockIdx.x * blockDim.x + threadIdx.x;
    if (i < n) p[i] = 0.0f;
}

// final argmax over proj partials + fused embed gather/split for next step
__global__ void argmax_final(float* __restrict__ out,
                             const float* __restrict__ embed,
                             int t, int mode) {
    const int b = blockIdx.x;
    const int tid = threadIdx.x;
    float bv = -FLT_MAX;
    int bi = 0x7fffffff;
    for (int i = tid; i < NPART; i += 256) {
        float v = g_pv[i * B + b];
        int   ix = g_pi[i * B + b];
        if (v > bv || (v == bv && ix < bi)) { bv = v; bi = ix; }
    }
    __shared__ float sv[256];
    __shared__ int   si[256];
    sv[tid] = bv;
    si[tid] = bi;
    __syncthreads();
    for (int s = 128; s > 0; s >>= 1) {
        if (tid < s) {
            float ov = sv[tid + s];
            int   oi = si[tid + s];
            if (ov > sv[tid] || (ov == sv[tid] && oi < si[tid])) {
                sv[tid] = ov;
                si[tid] = oi;
            }
        }
        __syncthreads();
    }
    const int sym = si[0];
    if (tid == 0 && mode)
        out[(size_t)B * T * V + (size_t)b * T + t] = (float)sym;
    const float4* erow = reinterpret_cast<const float4*>(embed + (size_t)sym * H);
    float4 v = erow[tid];
    int j = tid * 4;
    __half hi, lo;
    split_pair(v.x, hi, lo); g_xh[b * H + j]     = hi; g_xl[b * H + j]     = lo;
    split_pair(v.y, hi, lo); g_xh[b * H + j + 1] = hi; g_xl[b * H + j + 1] = lo;
    split_pair(v.z, hi, lo); g_xh[b * H + j + 2] = hi; g_xl[b * H + j + 2] = lo;
    split_pair(v.w, hi, lo); g_xh[b * H + j + 3] = hi; g_xl[b * H + j + 3] = lo;
}

// ---------------- launch ----------------------------------------------------------
extern "C" void kernel_launch(void* const* d_in, const int* in_sizes, int n_in,
                              void* d_out, int out_size) {
    const float* h0    = (const float*)d_in[1];
    const float* c0    = (const float*)d_in[2];
    const float* embed = (const float*)d_in[5];
    const float* w_ih  = (const float*)d_in[6];
    const float* w_hh  = (const float*)d_in[7];
    const float* b_ih  = (const float*)d_in[8];
    const float* b_hh  = (const float*)d_in[9];
    const float* w_out = (const float*)d_in[10];
    const float* b_out = (const float*)d_in[11];
    float* out = (float*)d_out;

    static int attr_done = 0;
    if (!attr_done) {
        cudaFuncSetAttribute(proj_tc, cudaFuncAttributeMaxDynamicSharedMemorySize, DSMEM_P);
        cudaFuncSetAttribute(lstm_fused, cudaFuncAttributeMaxDynamicSharedMemorySize, DSMEM_L);
        attr_done = 1;
    }

    const long long BTV = (long long)B * T * V;
    long long extra = (long long)out_size - BTV;
    int mode = (extra >= (long long)(B * T)) ? 1 : 0;

    init_kernel<<<(B * H + 511) / 512, 512>>>(h0, c0, embed, out, mode);

    split_weights<<<(V * H / 4 + 255) / 256, 256>>>(w_out, 0, V * H / 4);
    split_weights<<<(G4 * H / 4 + 255) / 256, 256>>>(w_ih, 1, G4 * H / 4);
    split_weights<<<(G4 * H / 4 + 255) / 256, 256>>>(w_hh, 2, G4 * H / 4);

    long long zstart = BTV + (mode ? (long long)(B * T) : 0);
    long long zcount = (long long)out_size - zstart;
    if (zcount > 0)
        fill_zero<<<(int)((zcount + 255) / 256), 256>>>(out + zstart, (int)zcount);

    proj_tc<<<V / 128, 256, DSMEM_P>>>(1, out, 0, b_out);

    for (int t = 1; t < T; t++) {
        lstm_fused<<<128, 256, DSMEM_L>>>(b_ih, b_hh);
        proj_tc<<<V / 128, 256, DSMEM_P>>>(0, out, t, b_out);
        argmax_final<<<B, 256>>>(out, embed, t, mode);
    }
}

// round 14
// speedup vs baseline: 1.1212x; 1.1212x over previous
#include <cuda_runtime.h>
#include <cuda_fp16.h>
#include <mma.h>
#include <cstdint>
#include <cfloat>

using namespace nvcuda;

#define B   64
#define H   1024
#define V   32000
#define T   40
#define G4  4096
#define SOS 1

#define KC   64
#define PE   72                     // smem pitch in half elements
#define ROWB 144                    // pitch bytes
#define NST  (H / KC)               // 16 stages
#define NPART (V / 128)             // 250 proj blocks

// ---- LSTM geometry (BM=64) ----
#define ARRB64 (64 * ROWB)          // 9216
#define STG64  (4 * ARRB64)         // 36864
#define DSMEM_L (2 * STG64)         // 73728

// ---- proj geometry (BM=128) ----
#define ARRB128 (128 * ROWB)        // 18432
#define STG128  (2 * ARRB128 + 2 * ARRB64)   // 55296
#define DSMEM_P (2 * STG128)        // 110592

// ---------------- persistent device state (device-code access ONLY) ----------
__device__ __align__(16) __half g_Wout_h[(size_t)V * H];
__device__ __align__(16) __half g_Wout_l[(size_t)V * H];
__device__ __align__(16) __half g_Wih_h[(size_t)G4 * H];
__device__ __align__(16) __half g_Wih_l[(size_t)G4 * H];
__device__ __align__(16) __half g_Whh_h[(size_t)G4 * H];
__device__ __align__(16) __half g_Whh_l[(size_t)G4 * H];
__device__ __align__(16) __half g_xh[B * H],  g_xl[B * H];
__device__ __align__(16) __half g_hh[B * H],  g_hl[B * H];
__device__ float g_c[B * H];
__device__ float g_gp0[B * G4];
__device__ float g_gp1[B * G4];
__device__ float g_pv[NPART * B];   // proj partial argmax values
__device__ int   g_pi[NPART * B];   // proj partial argmax indices
__device__ int   g_arr;             // monotonic proj-block arrival counter

// ---------------- helpers ------------------------------------------------------
__device__ __forceinline__ uint32_t smem_u32(const void* p) {
    uint32_t a;
    asm("{ .reg .u64 t; cvta.to.shared.u64 t, %1; cvt.u32.u64 %0, t; }"
        : "=r"(a) : "l"(p));
    return a;
}
__device__ __forceinline__ void cp16(uint32_t s, const void* g) {
    asm volatile("cp.async.cg.shared.global [%0], [%1], 16;" :: "r"(s), "l"(g));
}
__device__ __forceinline__ void cp_commit() {
    asm volatile("cp.async.commit_group;" ::: "memory");
}
__device__ __forceinline__ void cp_wait1() {
    asm volatile("cp.async.wait_group 1;" ::: "memory");
}
__device__ __forceinline__ void cp_wait0() {
    asm volatile("cp.async.wait_group 0;" ::: "memory");
}
__device__ __forceinline__ void split_pair(float x, __half& hi, __half& lo) {
    hi = __float2half_rn(x);
    lo = __float2half_rn(x - __half2float(hi));
}

// ---------------- LSTM GEMM mainloop (BM=64; round-11 verbatim) ----------------
__device__ __forceinline__ void gemm64(
    const __half* __restrict__ Ah, const __half* __restrict__ Al,
    const __half* __restrict__ Bh, const __half* __restrict__ Bl,
    int m0, char* sm, float* sC, __half* sCh)
{
    const int tid = threadIdx.x;
    const int wid = tid >> 5;
    const int ms = (wid & 3) * 16;
    const int nb = (wid >> 2) * 32;
    const uint32_t sbase = smem_u32(sm);

    const int r0 = tid >> 3,         c0 = tid & 7;
    const int r1 = (tid + 256) >> 3, c1 = tid & 7;
    const uint32_t so0 = (uint32_t)(r0 * ROWB + c0 * 16);
    const uint32_t so1 = (uint32_t)(r1 * ROWB + c1 * 16);

    wmma::fragment<wmma::accumulator, 16, 16, 16, float> fC[2];
    wmma::fragment<wmma::accumulator, 16, 16, 16, __half> fE[2];
    wmma::fill_fragment(fC[0], 0.0f);
    wmma::fill_fragment(fC[1], 0.0f);
    wmma::fill_fragment(fE[0], __float2half(0.0f));
    wmma::fill_fragment(fE[1], __float2half(0.0f));

#pragma unroll
    for (int s = 0; s < 2; s++) {
        const int kt = s * KC;
        const uint32_t sb = sbase + (uint32_t)s * STG64;
        const size_t ga0 = (size_t)(m0 + r0) * H + kt + c0 * 8;
        const size_t ga1 = (size_t)(m0 + r1) * H + kt + c1 * 8;
        const size_t gb0 = (size_t)r0 * H + kt + c0 * 8;
        const size_t gb1 = (size_t)r1 * H + kt + c1 * 8;
        cp16(sb + 0 * ARRB64 + so0, Ah + ga0);  cp16(sb + 0 * ARRB64 + so1, Ah + ga1);
        cp16(sb + 1 * ARRB64 + so0, Al + ga0);  cp16(sb + 1 * ARRB64 + so1, Al + ga1);
        cp16(sb + 2 * ARRB64 + so0, Bh + gb0);  cp16(sb + 2 * ARRB64 + so1, Bh + gb1);
        cp16(sb + 3 * ARRB64 + so0, Bl + gb0);  cp16(sb + 3 * ARRB64 + so1, Bl + gb1);
        cp_commit();
    }

    for (int s = 0; s < NST; s++) {
        if (s < NST - 1) cp_wait1(); else cp_wait0();
        __syncthreads();

        const __half* st =
            reinterpret_cast<const __half*>(sm + (size_t)(s & 1) * STG64);
        const __half* sAh = st;
        const __half* sAl = st + ARRB64 / 2;
        const __half* sBh = st + 2 * (ARRB64 / 2);
        const __half* sBl = st + 3 * (ARRB64 / 2);

#pragma unroll
        for (int ks = 0; ks < KC; ks += 16) {
            wmma::fragment<wmma::matrix_a, 16, 16, 16, __half,
                           wmma::row_major> fAh, fAl;
            wmma::load_matrix_sync(fAh, sAh + ms * PE + ks, PE);
            wmma::load_matrix_sync(fAl, sAl + ms * PE + ks, PE);
#pragma unroll
            for (int j = 0; j < 2; j++) {
                wmma::fragment<wmma::matrix_b, 16, 16, 16, __half,
                               wmma::col_major> fBh, fBl;
                const int nr = nb + j * 16;
                wmma::load_matrix_sync(fBh, sBh + nr * PE + ks, PE);
                wmma::load_matrix_sync(fBl, sBl + nr * PE + ks, PE);
                wmma::mma_sync(fC[j], fAh, fBh, fC[j]);
                wmma::mma_sync(fE[j], fAh, fBl, fE[j]);
                wmma::mma_sync(fE[j], fAl, fBh, fE[j]);
            }
        }
        __syncthreads();

        if (s + 2 < NST) {
            const int kt = (s + 2) * KC;
            const uint32_t sb = sbase + (uint32_t)(s & 1) * STG64;
            const size_t ga0 = (size_t)(m0 + r0) * H + kt + c0 * 8;
            const size_t ga1 = (size_t)(m0 + r1) * H + kt + c1 * 8;
            const size_t gb0 = (size_t)r0 * H + kt + c0 * 8;
            const size_t gb1 = (size_t)r1 * H + kt + c1 * 8;
            cp16(sb + 0 * ARRB64 + so0, Ah + ga0);  cp16(sb + 0 * ARRB64 + so1, Ah + ga1);
            cp16(sb + 1 * ARRB64 + so0, Al + ga0);  cp16(sb + 1 * ARRB64 + so1, Al + ga1);
            cp16(sb + 2 * ARRB64 + so0, Bh + gb0);  cp16(sb + 2 * ARRB64 + so1, Bh + gb1);
            cp16(sb + 3 * ARRB64 + so0, Bl + gb0);  cp16(sb + 3 * ARRB64 + so1, Bl + gb1);
            cp_commit();
        }
    }

    wmma::store_matrix_sync(sC + ms * 68 + nb,       fC[0], 68, wmma::mem_row_major);
    wmma::store_matrix_sync(sC + ms * 68 + nb + 16,  fC[1], 68, wmma::mem_row_major);
    wmma::store_matrix_sync(sCh + ms * 72 + nb,      fE[0], 72, wmma::mem_row_major);
    wmma::store_matrix_sync(sCh + ms * 72 + nb + 16, fE[1], 72, wmma::mem_row_major);
    __syncthreads();
}

// ---------------- proj GEMM mainloop (BM=128; round-11 verbatim) ---------------
__device__ __forceinline__ void gemm128(
    const __half* __restrict__ Ah, const __half* __restrict__ Al,
    const __half* __restrict__ Bh, const __half* __restrict__ Bl,
    int m0, char* sm, float* sC, __half* sCh)
{
    const int tid = threadIdx.x;
    const int wid = tid >> 5;
    const int ms = (wid & 3) * 32;
    const int nb = (wid >> 2) * 32;
    const uint32_t sbase = smem_u32(sm);

    const int c0 = tid & 7;
    const uint32_t soA[4] = {
        (uint32_t)(((tid + 0)   >> 3) * ROWB + c0 * 16),
        (uint32_t)(((tid + 256) >> 3) * ROWB + c0 * 16),
        (uint32_t)(((tid + 512) >> 3) * ROWB + c0 * 16),
        (uint32_t)(((tid + 768) >> 3) * ROWB + c0 * 16)
    };
    const int rA[4] = { (tid + 0) >> 3, (tid + 256) >> 3,
                        (tid + 512) >> 3, (tid + 768) >> 3 };

    wmma::fragment<wmma::accumulator, 16, 16, 16, float> fC[2][2];
    wmma::fragment<wmma::accumulator, 16, 16, 16, __half> fE[2][2];
#pragma unroll
    for (int i = 0; i < 2; i++)
#pragma unroll
        for (int j = 0; j < 2; j++) {
            wmma::fill_fragment(fC[i][j], 0.0f);
            wmma::fill_fragment(fE[i][j], __float2half(0.0f));
        }

#pragma unroll
    for (int s = 0; s < 2; s++) {
        const int kt = s * KC;
        const uint32_t sb = sbase + (uint32_t)s * STG128;
#pragma unroll
        for (int v = 0; v < 4; v++) {
            const size_t ga = (size_t)(m0 + rA[v]) * H + kt + c0 * 8;
            cp16(sb + 0 * ARRB128 + soA[v], Ah + ga);
            cp16(sb + 1 * ARRB128 + soA[v], Al + ga);
        }
#pragma unroll
        for (int v = 0; v < 2; v++) {
            const size_t gb = (size_t)rA[v] * H + kt + c0 * 8;
            cp16(sb + 2 * ARRB128 + soA[v], Bh + gb);
            cp16(sb + 2 * ARRB128 + ARRB64 + soA[v], Bl + gb);
        }
        cp_commit();
    }

    for (int s = 0; s < NST; s++) {
        if (s < NST - 1) cp_wait1(); else cp_wait0();
        __syncthreads();

        const __half* st =
            reinterpret_cast<const __half*>(sm + (size_t)(s & 1) * STG128);
        const __half* sAh = st;
        const __half* sAl = st + ARRB128 / 2;
        const __half* sBh = st + 2 * (ARRB128 / 2);
        const __half* sBl = st + 2 * (ARRB128 / 2) + ARRB64 / 2;

#pragma unroll
        for (int ks = 0; ks < KC; ks += 16) {
            wmma::fragment<wmma::matrix_a, 16, 16, 16, __half,
                           wmma::row_major> fAh[2], fAl[2];
#pragma unroll
            for (int i = 0; i < 2; i++) {
                wmma::load_matrix_sync(fAh[i], sAh + (ms + i * 16) * PE + ks, PE);
                wmma::load_matrix_sync(fAl[i], sAl + (ms + i * 16) * PE + ks, PE);
            }
#pragma unroll
            for (int j = 0; j < 2; j++) {
                wmma::fragment<wmma::matrix_b, 16, 16, 16, __half,
                               wmma::col_major> fBh, fBl;
                const int nr = nb + j * 16;
                wmma::load_matrix_sync(fBh, sBh + nr * PE + ks, PE);
                wmma::load_matrix_sync(fBl, sBl + nr * PE + ks, PE);
#pragma unroll
                for (int i = 0; i < 2; i++) {
                    wmma::mma_sync(fC[i][j], fAh[i], fBh, fC[i][j]);
                    wmma::mma_sync(fE[i][j], fAh[i], fBl, fE[i][j]);
                    wmma::mma_sync(fE[i][j], fAl[i], fBh, fE[i][j]);
                }
            }
        }
        __syncthreads();

        if (s + 2 < NST) {
            const int kt = (s + 2) * KC;
            const uint32_t sb = sbase + (uint32_t)(s & 1) * STG128;
#pragma unroll
            for (int v = 0; v < 4; v++) {
                const size_t ga = (size_t)(m0 + rA[v]) * H + kt + c0 * 8;
                cp16(sb + 0 * ARRB128 + soA[v], Ah + ga);
                cp16(sb + 1 * ARRB128 + soA[v], Al + ga);
            }
#pragma unroll
            for (int v = 0; v < 2; v++) {
                const size_t gb = (size_t)rA[v] * H + kt + c0 * 8;
                cp16(sb + 2 * ARRB128 + soA[v], Bh + gb);
                cp16(sb + 2 * ARRB128 + ARRB64 + soA[v], Bl + gb);
            }
            cp_commit();
        }
    }

#pragma unroll
    for (int i = 0; i < 2; i++)
#pragma unroll
        for (int j = 0; j < 2; j++) {
            wmma::store_matrix_sync(sC + (ms + i * 16) * 68 + nb + j * 16,
                                    fC[i][j], 68, wmma::mem_row_major);
            wmma::store_matrix_sync(sCh + (ms + i * 16) * 72 + nb + j * 16,
                                    fE[i][j], 72, wmma::mem_row_major);
        }
    __syncthreads();
}

// ---------------- projection kernel + partial argmax + in-kernel final ---------
// do_final=0 on the t=0 call: dec0's argmax must NOT overwrite x (step 1 uses
// embed[SOS] per the reference carry). Counter still advances by 250 per call;
// arr_target = 250 * (call index + 1) stays correct.
__global__ __launch_bounds__(256, 2)
void proj_tc(int useX0, float* __restrict__ dst, int t,
             const float* __restrict__ bias, const float* __restrict__ embed,
             int mode, int do_final, int arr_target)
{
    extern __shared__ char sm[];
    float* sC  = reinterpret_cast<float*>(sm);
    __half* sCh = reinterpret_cast<__half*>(sm + 128 * 68 * 4);
    __shared__ float sBias[128];
    __shared__ float sPV[256];
    __shared__ int   sPI[256];

    const int tid = threadIdx.x;
    const int m0 = blockIdx.x * 128;
    if (tid < 128) sBias[tid] = bias[m0 + tid];

    const __half* Bh = useX0 ? g_xh : g_hh;
    const __half* Bl = useX0 ? g_xl : g_hl;
    gemm128(g_Wout_h, g_Wout_l, Bh, Bl, m0, sm, sC, sCh);

    // single-pass: finalize logit, write to gmem AND back into sC
    const int ml = tid & 127;
    const int nlb = tid >> 7;
    const int gm = m0 + ml;
    const float bb = sBias[ml];
#pragma unroll
    for (int r = 0; r < 32; r++) {
        const int n = nlb + r * 2;
        float v = sC[ml * 68 + n] + __half2float(sCh[ml * 72 + n]) + bb;
        dst[((size_t)n * T + t) * (size_t)V + gm] = v;
        sC[ml * 68 + n] = v;
    }
    __syncthreads();

    // partial argmax over this block's 128 vocab rows, per batch column
    const int n = tid & 63, q = tid >> 6;
    float bv = -FLT_MAX;
    int bi = 0;
    for (int r = q * 32; r < q * 32 + 32; r++) {
        float v = sC[r * 68 + n];
        if (v > bv) { bv = v; bi = m0 + r; }
    }
    sPV[tid] = bv;
    sPI[tid] = bi;
    __syncthreads();
    if (tid < 64) {
        float v0 = sPV[tid];
        int   i0 = sPI[tid];
#pragma unroll
        for (int qq = 1; qq < 4; qq++) {
            float v = sPV[tid + qq * 64];
            int   i = sPI[tid + qq * 64];
            if (v > v0 || (v == v0 && i < i0)) { v0 = v; i0 = i; }
        }
        g_pv[blockIdx.x * B + tid] = v0;
        g_pi[blockIdx.x * B + tid] = i0;
    }
    __syncthreads();
    if (tid == 0) {
        __threadfence();
        atomicAdd(&g_arr, 1);
    }

    if (!do_final || blockIdx.x >= B) return;

    // ---- final argmax for batch b = blockIdx.x ----
    const int b = blockIdx.x;
    if (tid == 0) {
        while (atomicAdd(&g_arr, 0) < arr_target) __nanosleep(64);
    }
    __syncthreads();
    __threadfence();

    float bv2 = -FLT_MAX;
    int bi2 = 0x7fffffff;
    if (tid < NPART) {
        bv2 = g_pv[tid * B + b];
        bi2 = g_pi[tid * B + b];
    }
    sPV[tid] = bv2;
    sPI[tid] = bi2;
    __syncthreads();
    for (int s = 128; s > 0; s >>= 1) {
        if (tid < s) {
            float ov = sPV[tid + s];
            int   oi = sPI[tid + s];
            if (ov > sPV[tid] || (ov == sPV[tid] && oi < sPI[tid])) {
                sPV[tid] = ov;
                sPI[tid] = oi;
            }
        }
        __syncthreads();
    }
    const int sym = sPI[0];
    if (tid == 0 && mode)
        dst[(size_t)B * T * V + (size_t)b * T + t] = (float)sym;
    // gather + fp16-split embed[sym] -> x for next LSTM step
    const float4* erow = reinterpret_cast<const float4*>(embed + (size_t)sym * H);
    float4 v = erow[tid];
    int j = tid * 4;
    __half hi, lo;
    split_pair(v.x, hi, lo); g_xh[b * H + j]     = hi; g_xl[b * H + j]     = lo;
    split_pair(v.y, hi, lo); g_xh[b * H + j + 1] = hi; g_xl[b * H + j + 1] = lo;
    split_pair(v.z, hi, lo); g_xh[b * H + j + 2] = hi; g_xl[b * H + j + 2] = lo;
    split_pair(v.w, hi, lo); g_xh[b * H + j + 3] = hi; g_xl[b * H + j + 3] = lo;
}

// ---------------- LSTM gates kernel (pass-parallel, BM=64, round-11) -----------
__global__ __launch_bounds__(256, 2)
void lstm_tc()
{
    extern __shared__ char sm[];
    float* sC  = reinterpret_cast<float*>(sm);
    __half* sCh = reinterpret_cast<__half*>(sm + 64 * 68 * 4);
    const int pass = blockIdx.x >> 6;
    const int m0 = (blockIdx.x & 63) * 64;

    const __half* Ah = pass ? g_Whh_h : g_Wih_h;
    const __half* Al = pass ? g_Whh_l : g_Wih_l;
    const __half* Bh = pass ? g_hh : g_xh;
    const __half* Bl = pass ? g_hl : g_xl;
    gemm64(Ah, Al, Bh, Bl, m0, sm, sC, sCh);

    float* gp = pass ? g_gp1 : g_gp0;
    const int ml = threadIdx.x & 63;
    const int nlb = threadIdx.x >> 6;
    const int gm = m0 + ml;
#pragma unroll
    for (int r = 0; r < 16; r++) {
        const int n = nlb + r * 4;
        gp[(size_t)n * G4 + gm] = sC[ml * 68 + n] + __half2float(sCh[ml * 72 + n]);
    }
}

// ---------------- weight pre-split ---------------------------------------------
__global__ void split_weights(const float* __restrict__ src, int which, int n4) {
    int i4 = blockIdx.x * blockDim.x + threadIdx.x;
    if (i4 >= n4) return;
    __half* dh;
    __half* dl;
    if (which == 0)      { dh = g_Wout_h; dl = g_Wout_l; }
    else if (which == 1) { dh = g_Wih_h;  dl = g_Wih_l; }
    else                 { dh = g_Whh_h;  dl = g_Whh_l; }
    float4 v = reinterpret_cast<const float4*>(src)[i4];
    __half h0, l0, h1, l1, h2, l2, h3, l3;
    split_pair(v.x, h0, l0);
    split_pair(v.y, h1, l1);
    split_pair(v.z, h2, l2);
    split_pair(v.w, h3, l3);
    size_t o = (size_t)i4 * 4;
    dh[o] = h0; dh[o + 1] = h1; dh[o + 2] = h2; dh[o + 3] = h3;
    dl[o] = l0; dl[o + 1] = l1; dl[o + 2] = l2; dl[o + 3] = l3;
}

// ---------------- small kernels --------------------------------------------------
__global__ void init_kernel(const float* __restrict__ h0,
                            const float* __restrict__ c0,
                            const float* __restrict__ embed,
                            float* __restrict__ out, int mode) {
    int idx = blockIdx.x * blockDim.x + threadIdx.x;
    if (idx < B * H) {
        g_c[idx] = c0[idx];
        __half hi, lo;
        split_pair(h0[idx], hi, lo);
        g_hh[idx] = hi;
        g_hl[idx] = lo;
        split_pair(embed[(size_t)SOS * H + (idx & (H - 1))], hi, lo);
        g_xh[idx] = hi;
        g_xl[idx] = lo;
    }
    if (idx == 0) g_arr = 0;
    if (idx < B && mode)
        out[(size_t)B * T * V + (size_t)idx * T + 0] = (float)SOS;
}

__global__ void fill_zero(float* __restrict__ p, int n) {
    int i = blockIdx.x * blockDim.x + threadIdx.x;
    if (i < n) p[i] = 0.0f;
}

__global__ void lstm_act_kernel(const float* __restrict__ b_ih,
                                const float* __restrict__ b_hh) {
    int idx = blockIdx.x * blockDim.x + threadIdx.x;   // B*H
    int b = idx >> 10;
    int j = idx & (H - 1);
    const size_t base = (size_t)b * G4;
    float gi = g_gp0[base + j]        + g_gp1[base + j]        + b_ih[j]        + b_hh[j];
    float gf = g_gp0[base + j + 1024] + g_gp1[base + j + 1024] + b_ih[j + 1024] + b_hh[j + 1024];
    float gg = g_gp0[base + j + 2048] + g_gp1[base + j + 2048] + b_ih[j + 2048] + b_hh[j + 2048];
    float go = g_gp0[base + j + 3072] + g_gp1[base + j + 3072] + b_ih[j + 3072] + b_hh[j + 3072];
    float c  = g_c[idx];
    float si = 1.0f / (1.0f + expf(-gi));
    float sf = 1.0f / (1.0f + expf(-gf));
    float so = 1.0f / (1.0f + expf(-go));
    float c2 = sf * c + si * tanhf(gg);
    float h2 = so * tanhf(c2);
    g_c[idx] = c2;
    __half hi, lo;
    split_pair(h2, hi, lo);
    g_hh[idx] = hi;
    g_hl[idx] = lo;
}

// ---------------- launch ----------------------------------------------------------
extern "C" void kernel_launch(void* const* d_in, const int* in_sizes, int n_in,
                              void* d_out, int out_size) {
    const float* h0    = (const float*)d_in[1];
    const float* c0    = (const float*)d_in[2];
    const float* embed = (const float*)d_in[5];
    const float* w_ih  = (const float*)d_in[6];
    const float* w_hh  = (const float*)d_in[7];
    const float* b_ih  = (const float*)d_in[8];
    const float* b_hh  = (const float*)d_in[9];
    const float* w_out = (const float*)d_in[10];
    const float* b_out = (const float*)d_in[11];
    float* out = (float*)d_out;

    static int attr_done = 0;
    if (!attr_done) {
        cudaFuncSetAttribute(proj_tc, cudaFuncAttributeMaxDynamicSharedMemorySize, DSMEM_P);
        cudaFuncSetAttribute(lstm_tc, cudaFuncAttributeMaxDynamicSharedMemorySize, DSMEM_L);
        attr_done = 1;
    }

    const long long BTV = (long long)B * T * V;
    long long extra = (long long)out_size - BTV;
    int mode = (extra >= (long long)(B * T)) ? 1 : 0;

    init_kernel<<<(B * H + 511) / 512, 512>>>(h0, c0, embed, out, mode);

    split_weights<<<(V * H / 4 + 255) / 256, 256>>>(w_out, 0, V * H / 4);
    split_weights<<<(G4 * H / 4 + 255) / 256, 256>>>(w_ih, 1, G4 * H / 4);
    split_weights<<<(G4 * H / 4 + 255) / 256, 256>>>(w_hh, 2, G4 * H / 4);

    long long zstart = BTV + (mode ? (long long)(B * T) : 0);
    long long zcount = (long long)out_size - zstart;
    if (zcount > 0)
        fill_zero<<<(int)((zcount + 255) / 256), 256>>>(out + zstart, (int)zcount);

    // t = 0: decs[0] = W*embed[SOS]; step 1's x stays embed[SOS] (carry semantics)
    // -> do_final = 0 here.
    proj_tc<<<V / 128, 256, DSMEM_P>>>(1, out, 0, b_out, embed, mode, 0, 250);

    for (int t = 1; t < T; t++) {
        lstm_tc<<<128, 256, DSMEM_L>>>();
        lstm_act_kernel<<<(B * H) / 256, 256>>>(b_ih, b_hh);
        // argmax(decs[t]) feeds x for step t+1 (and symbol_outs[t+1], unwritten
        // at t=T-1 which matches: last symbol emitted is argmax(decs[T-2])).
        proj_tc<<<V / 128, 256, DSMEM_P>>>(0, out, t, b_out, embed, mode,
                                           1, 250 * (t + 1));
    }
}

// round 15
// speedup vs baseline: 1.1214x; 1.0001x over previous
#include <cuda_runtime.h>
#include <cuda_fp16.h>
#include <mma.h>
#include <cstdint>
#include <cfloat>

using namespace nvcuda;

#define B   64
#define H   1024
#define V   32000
#define T   40
#define G4  4096
#define SOS 1

#define KC   64
#define PE   72                     // smem pitch in half elements
#define ROWB 144                    // pitch bytes
#define NST  (H / KC)               // 16 stages
#define NPART (V / 128)             // 250 proj blocks

// ---- LSTM geometry (BM=64, 3-stage ring) ----
#define ARRB64 (64 * ROWB)          // 9216
#define STG64  (4 * ARRB64)         // 36864
#define DSMEM_L (3 * STG64)         // 110592

// ---- proj geometry (BM=128, 2-stage) ----
#define ARRB128 (128 * ROWB)        // 18432
#define STG128  (2 * ARRB128 + 2 * ARRB64)   // 55296
#define DSMEM_P (2 * STG128)        // 110592

// ---------------- persistent device state (device-code access ONLY) ----------
__device__ __align__(16) __half g_Wout_h[(size_t)V * H];
__device__ __align__(16) __half g_Wout_l[(size_t)V * H];
__device__ __align__(16) __half g_Wih_h[(size_t)G4 * H];
__device__ __align__(16) __half g_Wih_l[(size_t)G4 * H];
__device__ __align__(16) __half g_Whh_h[(size_t)G4 * H];
__device__ __align__(16) __half g_Whh_l[(size_t)G4 * H];
__device__ __align__(16) __half g_xh[B * H],  g_xl[B * H];
__device__ __align__(16) __half g_hh[B * H],  g_hl[B * H];
__device__ float g_c[B * H];
__device__ float g_gp0[B * G4];
__device__ float g_gp1[B * G4];
__device__ float g_pv[NPART * B];   // proj partial argmax values
__device__ int   g_pi[NPART * B];   // proj partial argmax indices

// ---------------- helpers ------------------------------------------------------
__device__ __forceinline__ uint32_t smem_u32(const void* p) {
    uint32_t a;
    asm("{ .reg .u64 t; cvta.to.shared.u64 t, %1; cvt.u32.u64 %0, t; }"
        : "=r"(a) : "l"(p));
    return a;
}
__device__ __forceinline__ void cp16(uint32_t s, const void* g) {
    asm volatile("cp.async.cg.shared.global [%0], [%1], 16;" :: "r"(s), "l"(g));
}
__device__ __forceinline__ void cp_commit() {
    asm volatile("cp.async.commit_group;" ::: "memory");
}
__device__ __forceinline__ void cp_wait2() {
    asm volatile("cp.async.wait_group 2;" ::: "memory");
}
__device__ __forceinline__ void cp_wait1() {
    asm volatile("cp.async.wait_group 1;" ::: "memory");
}
__device__ __forceinline__ void cp_wait0() {
    asm volatile("cp.async.wait_group 0;" ::: "memory");
}
__device__ __forceinline__ void split_pair(float x, __half& hi, __half& lo) {
    hi = __float2half_rn(x);
    lo = __float2half_rn(x - __half2float(hi));
}

// ---------------- LSTM GEMM mainloop (BM=64, 3-stage ring) ---------------------
__device__ __forceinline__ void gemm64(
    const __half* __restrict__ Ah, const __half* __restrict__ Al,
    const __half* __restrict__ Bh, const __half* __restrict__ Bl,
    int m0, char* sm, float* sC, __half* sCh)
{
    const int tid = threadIdx.x;
    const int wid = tid >> 5;
    const int ms = (wid & 3) * 16;
    const int nb = (wid >> 2) * 32;
    const uint32_t sbase = smem_u32(sm);

    const int r0 = tid >> 3,         c0 = tid & 7;
    const int r1 = (tid + 256) >> 3, c1 = tid & 7;
    const uint32_t so0 = (uint32_t)(r0 * ROWB + c0 * 16);
    const uint32_t so1 = (uint32_t)(r1 * ROWB + c1 * 16);

    wmma::fragment<wmma::accumulator, 16, 16, 16, float> fC[2];
    wmma::fragment<wmma::accumulator, 16, 16, 16, __half> fE[2];
    wmma::fill_fragment(fC[0], 0.0f);
    wmma::fill_fragment(fC[1], 0.0f);
    wmma::fill_fragment(fE[0], __float2half(0.0f));
    wmma::fill_fragment(fE[1], __float2half(0.0f));

    auto load_stage = [&](int s, int slot) {
        const int kt = s * KC;
        const uint32_t sb = sbase + (uint32_t)slot * STG64;
        const size_t ga0 = (size_t)(m0 + r0) * H + kt + c0 * 8;
        const size_t ga1 = (size_t)(m0 + r1) * H + kt + c1 * 8;
        const size_t gb0 = (size_t)r0 * H + kt + c0 * 8;
        const size_t gb1 = (size_t)r1 * H + kt + c1 * 8;
        cp16(sb + 0 * ARRB64 + so0, Ah + ga0);  cp16(sb + 0 * ARRB64 + so1, Ah + ga1);
        cp16(sb + 1 * ARRB64 + so0, Al + ga0);  cp16(sb + 1 * ARRB64 + so1, Al + ga1);
        cp16(sb + 2 * ARRB64 + so0, Bh + gb0);  cp16(sb + 2 * ARRB64 + so1, Bh + gb1);
        cp16(sb + 3 * ARRB64 + so0, Bl + gb0);  cp16(sb + 3 * ARRB64 + so1, Bl + gb1);
        cp_commit();
    };

    // prologue: stages 0,1 into slots 0,1
    load_stage(0, 0);
    load_stage(1, 1);

    for (int s = 0; s < NST; s++) {
        if (s + 2 < NST) {
            load_stage(s + 2, (s + 2) % 3);
            cp_wait2();
        } else if (s + 1 < NST) {
            cp_wait1();
        } else {
            cp_wait0();
        }
        __syncthreads();

        const __half* st =
            reinterpret_cast<const __half*>(sm + (size_t)(s % 3) * STG64);
        const __half* sAh = st;
        const __half* sAl = st + ARRB64 / 2;
        const __half* sBh = st + 2 * (ARRB64 / 2);
        const __half* sBl = st + 3 * (ARRB64 / 2);

#pragma unroll
        for (int ks = 0; ks < KC; ks += 16) {
            wmma::fragment<wmma::matrix_a, 16, 16, 16, __half,
                           wmma::row_major> fAh, fAl;
            wmma::load_matrix_sync(fAh, sAh + ms * PE + ks, PE);
            wmma::load_matrix_sync(fAl, sAl + ms * PE + ks, PE);
#pragma unroll
            for (int j = 0; j < 2; j++) {
                wmma::fragment<wmma::matrix_b, 16, 16, 16, __half,
                               wmma::col_major> fBh, fBl;
                const int nr = nb + j * 16;
                wmma::load_matrix_sync(fBh, sBh + nr * PE + ks, PE);
                wmma::load_matrix_sync(fBl, sBl + nr * PE + ks, PE);
                wmma::mma_sync(fC[j], fAh, fBh, fC[j]);
                wmma::mma_sync(fE[j], fAh, fBl, fE[j]);
                wmma::mma_sync(fE[j], fAl, fBh, fE[j]);
            }
        }
        __syncthreads();
    }

    wmma::store_matrix_sync(sC + ms * 68 + nb,       fC[0], 68, wmma::mem_row_major);
    wmma::store_matrix_sync(sC + ms * 68 + nb + 16,  fC[1], 68, wmma::mem_row_major);
    wmma::store_matrix_sync(sCh + ms * 72 + nb,      fE[0], 72, wmma::mem_row_major);
    wmma::store_matrix_sync(sCh + ms * 72 + nb + 16, fE[1], 72, wmma::mem_row_major);
    __syncthreads();
}

// ---------------- proj GEMM mainloop (BM=128; round-11 verbatim) ---------------
__device__ __forceinline__ void gemm128(
    const __half* __restrict__ Ah, const __half* __restrict__ Al,
    const __half* __restrict__ Bh, const __half* __restrict__ Bl,
    int m0, char* sm, float* sC, __half* sCh)
{
    const int tid = threadIdx.x;
    const int wid = tid >> 5;
    const int ms = (wid & 3) * 32;
    const int nb = (wid >> 2) * 32;
    const uint32_t sbase = smem_u32(sm);

    const int c0 = tid & 7;
    const uint32_t soA[4] = {
        (uint32_t)(((tid + 0)   >> 3) * ROWB + c0 * 16),
        (uint32_t)(((tid + 256) >> 3) * ROWB + c0 * 16),
        (uint32_t)(((tid + 512) >> 3) * ROWB + c0 * 16),
        (uint32_t)(((tid + 768) >> 3) * ROWB + c0 * 16)
    };
    const int rA[4] = { (tid + 0) >> 3, (tid + 256) >> 3,
                        (tid + 512) >> 3, (tid + 768) >> 3 };

    wmma::fragment<wmma::accumulator, 16, 16, 16, float> fC[2][2];
    wmma::fragment<wmma::accumulator, 16, 16, 16, __half> fE[2][2];
#pragma unroll
    for (int i = 0; i < 2; i++)
#pragma unroll
        for (int j = 0; j < 2; j++) {
            wmma::fill_fragment(fC[i][j], 0.0f);
            wmma::fill_fragment(fE[i][j], __float2half(0.0f));
        }

#pragma unroll
    for (int s = 0; s < 2; s++) {
        const int kt = s * KC;
        const uint32_t sb = sbase + (uint32_t)s * STG128;
#pragma unroll
        for (int v = 0; v < 4; v++) {
            const size_t ga = (size_t)(m0 + rA[v]) * H + kt + c0 * 8;
            cp16(sb + 0 * ARRB128 + soA[v], Ah + ga);
            cp16(sb + 1 * ARRB128 + soA[v], Al + ga);
        }
#pragma unroll
        for (int v = 0; v < 2; v++) {
            const size_t gb = (size_t)rA[v] * H + kt + c0 * 8;
            cp16(sb + 2 * ARRB128 + soA[v], Bh + gb);
            cp16(sb + 2 * ARRB128 + ARRB64 + soA[v], Bl + gb);
        }
        cp_commit();
    }

    for (int s = 0; s < NST; s++) {
        if (s < NST - 1) cp_wait1(); else cp_wait0();
        __syncthreads();

        const __half* st =
            reinterpret_cast<const __half*>(sm + (size_t)(s & 1) * STG128);
        const __half* sAh = st;
        const __half* sAl = st + ARRB128 / 2;
        const __half* sBh = st + 2 * (ARRB128 / 2);
        const __half* sBl = st + 2 * (ARRB128 / 2) + ARRB64 / 2;

#pragma unroll
        for (int ks = 0; ks < KC; ks += 16) {
            wmma::fragment<wmma::matrix_a, 16, 16, 16, __half,
                           wmma::row_major> fAh[2], fAl[2];
#pragma unroll
            for (int i = 0; i < 2; i++) {
                wmma::load_matrix_sync(fAh[i], sAh + (ms + i * 16) * PE + ks, PE);
                wmma::load_matrix_sync(fAl[i], sAl + (ms + i * 16) * PE + ks, PE);
            }
#pragma unroll
            for (int j = 0; j < 2; j++) {
                wmma::fragment<wmma::matrix_b, 16, 16, 16, __half,
                               wmma::col_major> fBh, fBl;
                const int nr = nb + j * 16;
                wmma::load_matrix_sync(fBh, sBh + nr * PE + ks, PE);
                wmma::load_matrix_sync(fBl, sBl + nr * PE + ks, PE);
#pragma unroll
                for (int i = 0; i < 2; i++) {
                    wmma::mma_sync(fC[i][j], fAh[i], fBh, fC[i][j]);
                    wmma::mma_sync(fE[i][j], fAh[i], fBl, fE[i][j]);
                    wmma::mma_sync(fE[i][j], fAl[i], fBh, fE[i][j]);
                }
            }
        }
        __syncthreads();

        if (s + 2 < NST) {
            const int kt = (s + 2) * KC;
            const uint32_t sb = sbase + (uint32_t)(s & 1) * STG128;
#pragma unroll
            for (int v = 0; v < 4; v++) {
                const size_t ga = (size_t)(m0 + rA[v]) * H + kt + c0 * 8;
                cp16(sb + 0 * ARRB128 + soA[v], Ah + ga);
                cp16(sb + 1 * ARRB128 + soA[v], Al + ga);
            }
#pragma unroll
            for (int v = 0; v < 2; v++) {
                const size_t gb = (size_t)rA[v] * H + kt + c0 * 8;
                cp16(sb + 2 * ARRB128 + soA[v], Bh + gb);
                cp16(sb + 2 * ARRB128 + ARRB64 + soA[v], Bl + gb);
            }
            cp_commit();
        }
    }

#pragma unroll
    for (int i = 0; i < 2; i++)
#pragma unroll
        for (int j = 0; j < 2; j++) {
            wmma::store_matrix_sync(sC + (ms + i * 16) * 68 + nb + j * 16,
                                    fC[i][j], 68, wmma::mem_row_major);
            wmma::store_matrix_sync(sCh + (ms + i * 16) * 72 + nb + j * 16,
                                    fE[i][j], 72, wmma::mem_row_major);
        }
    __syncthreads();
}

// ---------------- projection kernel (BM=128, occ 2) + partial argmax -----------
__global__ __launch_bounds__(256, 2)
void proj_tc(int useX0, float* __restrict__ dst, int t,
             const float* __restrict__ bias)
{
    extern __shared__ char sm[];
    float* sC  = reinterpret_cast<float*>(sm);
    __half* sCh = reinterpret_cast<__half*>(sm + 128 * 68 * 4);
    __shared__ float sBias[128];
    __shared__ float sPV[256];
    __shared__ int   sPI[256];

    const int tid = threadIdx.x;
    const int m0 = blockIdx.x * 128;
    if (tid < 128) sBias[tid] = bias[m0 + tid];

    const __half* Bh = useX0 ? g_xh : g_hh;
    const __half* Bl = useX0 ? g_xl : g_hl;
    gemm128(g_Wout_h, g_Wout_l, Bh, Bl, m0, sm, sC, sCh);

    // single-pass: finalize logit, write to gmem AND back into sC
    const int ml = tid & 127;
    const int nlb = tid >> 7;
    const int gm = m0 + ml;
    const float bb = sBias[ml];
#pragma unroll
    for (int r = 0; r < 32; r++) {
        const int n = nlb + r * 2;
        float v = sC[ml * 68 + n] + __half2float(sCh[ml * 72 + n]) + bb;
        dst[((size_t)n * T + t) * (size_t)V + gm] = v;
        sC[ml * 68 + n] = v;
    }
    __syncthreads();

    const int n = tid & 63, q = tid >> 6;
    float bv = -FLT_MAX;
    int bi = 0;
    for (int r = q * 32; r < q * 32 + 32; r++) {
        float v = sC[r * 68 + n];
        if (v > bv) { bv = v; bi = m0 + r; }
    }
    sPV[tid] = bv;
    sPI[tid] = bi;
    __syncthreads();
    if (tid < 64) {
        float v0 = sPV[tid];
        int   i0 = sPI[tid];
#pragma unroll
        for (int qq = 1; qq < 4; qq++) {
            float v = sPV[tid + qq * 64];
            int   i = sPI[tid + qq * 64];
            if (v > v0 || (v == v0 && i < i0)) { v0 = v; i0 = i; }
        }
        g_pv[blockIdx.x * B + tid] = v0;
        g_pi[blockIdx.x * B + tid] = i0;
    }
}

// ---------------- LSTM gates kernel (pass-parallel, BM=64, occ 2) --------------
__global__ __launch_bounds__(256, 2)
void lstm_tc()
{
    extern __shared__ char sm[];
    float* sC  = reinterpret_cast<float*>(sm);
    __half* sCh = reinterpret_cast<__half*>(sm + 64 * 68 * 4);
    const int pass = blockIdx.x >> 6;
    const int m0 = (blockIdx.x & 63) * 64;

    const __half* Ah = pass ? g_Whh_h : g_Wih_h;
    const __half* Al = pass ? g_Whh_l : g_Wih_l;
    const __half* Bh = pass ? g_hh : g_xh;
    const __half* Bl = pass ? g_hl : g_xl;
    gemm64(Ah, Al, Bh, Bl, m0, sm, sC, sCh);

    float* gp = pass ? g_gp1 : g_gp0;
    const int ml = threadIdx.x & 63;
    const int nlb = threadIdx.x >> 6;
    const int gm = m0 + ml;
#pragma unroll
    for (int r = 0; r < 16; r++) {
        const int n = nlb + r * 4;
        gp[(size_t)n * G4 + gm] = sC[ml * 68 + n] + __half2float(sCh[ml * 72 + n]);
    }
}

// ---------------- weight pre-split ---------------------------------------------
__global__ void split_weights(const float* __restrict__ src, int which, int n4) {
    int i4 = blockIdx.x * blockDim.x + threadIdx.x;
    if (i4 >= n4) return;
    __half* dh;
    __half* dl;
    if (which == 0)      { dh = g_Wout_h; dl = g_Wout_l; }
    else if (which == 1) { dh = g_Wih_h;  dl = g_Wih_l; }
    else                 { dh = g_Whh_h;  dl = g_Whh_l; }
    float4 v = reinterpret_cast<const float4*>(src)[i4];
    __half h0, l0, h1, l1, h2, l2, h3, l3;
    split_pair(v.x, h0, l0);
    split_pair(v.y, h1, l1);
    split_pair(v.z, h2, l2);
    split_pair(v.w, h3, l3);
    size_t o = (size_t)i4 * 4;
    dh[o] = h0; dh[o + 1] = h1; dh[o + 2] = h2; dh[o + 3] = h3;
    dl[o] = l0; dl[o + 1] = l1; dl[o + 2] = l2; dl[o + 3] = l3;
}

// ---------------- small kernels --------------------------------------------------
__global__ void init_kernel(const float* __restrict__ h0,
                            const float* __restrict__ c0,
                            const float* __restrict__ embed,
                            float* __restrict__ out, int mode) {
    int idx = blockIdx.x * blockDim.x + threadIdx.x;
    if (idx < B * H) {
        g_c[idx] = c0[idx];
        __half hi, lo;
        split_pair(h0[idx], hi, lo);
        g_hh[idx] = hi;
        g_hl[idx] = lo;
        split_pair(embed[(size_t)SOS * H + (idx & (H - 1))], hi, lo);
        g_xh[idx] = hi;
        g_xl[idx] = lo;
    }
    if (idx < B && mode)
        out[(size_t)B * T * V + (size_t)idx * T + 0] = (float)SOS;
}

__global__ void fill_zero(float* __restrict__ p, int n) {
    int i = blockIdx.x * blockDim.x + threadIdx.x;
    if (i < n) p[i] = 0.0f;
}

__global__ void lstm_act_kernel(const float* __restrict__ b_ih,
                                const float* __restrict__ b_hh) {
    int idx = blockIdx.x * blockDim.x + threadIdx.x;   // B*H
    int b = idx >> 10;
    int j = idx & (H - 1);
    const size_t base = (size_t)b * G4;
    float gi = g_gp0[base + j]        + g_gp1[base + j]        + b_ih[j]        + b_hh[j];
    float gf = g_gp0[base + j + 1024] + g_gp1[base + j + 1024] + b_ih[j + 1024] + b_hh[j + 1024];
    float gg = g_gp0[base + j + 2048] + g_gp1[base + j + 2048] + b_ih[j + 2048] + b_hh[j + 2048];
    float go = g_gp0[base + j + 3072] + g_gp1[base + j + 3072] + b_ih[j + 3072] + b_hh[j + 3072];
    float c  = g_c[idx];
    float si = 1.0f / (1.0f + expf(-gi));
    float sf = 1.0f / (1.0f + expf(-gf));
    float so = 1.0f / (1.0f + expf(-go));
    float c2 = sf * c + si * tanhf(gg);
    float h2 = so * tanhf(c2);
    g_c[idx] = c2;
    __half hi, lo;
    split_pair(h2, hi, lo);
    g_hh[idx] = hi;
    g_hl[idx] = lo;
}

// final argmax over proj partials + fused embed gather/split for next step
__global__ void argmax_final(float* __restrict__ out,
                             const float* __restrict__ embed,
                             int t, int mode) {
    const int b = blockIdx.x;
    const int tid = threadIdx.x;
    float bv = -FLT_MAX;
    int bi = 0x7fffffff;
    for (int i = tid; i < NPART; i += 256) {
        float v = g_pv[i * B + b];
        int   ix = g_pi[i * B + b];
        if (v > bv || (v == bv && ix < bi)) { bv = v; bi = ix; }
    }
    __shared__ float sv[256];
    __shared__ int   si[256];
    sv[tid] = bv;
    si[tid] = bi;
    __syncthreads();
    for (int s = 128; s > 0; s >>= 1) {
        if (tid < s) {
            float ov = sv[tid + s];
            int   oi = si[tid + s];
            if (ov > sv[tid] || (ov == sv[tid] && oi < si[tid])) {
                sv[tid] = ov;
                si[tid] = oi;
            }
        }
        __syncthreads();
    }
    const int sym = si[0];
    if (tid == 0 && mode)
        out[(size_t)B * T * V + (size_t)b * T + t] = (float)sym;
    const float4* erow = reinterpret_cast<const float4*>(embed + (size_t)sym * H);
    float4 v = erow[tid];
    int j = tid * 4;
    __half hi, lo;
    split_pair(v.x, hi, lo); g_xh[b * H + j]     = hi; g_xl[b * H + j]     = lo;
    split_pair(v.y, hi, lo); g_xh[b * H + j + 1] = hi; g_xl[b * H + j + 1] = lo;
    split_pair(v.z, hi, lo); g_xh[b * H + j + 2] = hi; g_xl[b * H + j + 2] = lo;
    split_pair(v.w, hi, lo); g_xh[b * H + j + 3] = hi; g_xl[b * H + j + 3] = lo;
}

// ---------------- launch ----------------------------------------------------------
extern "C" void kernel_launch(void* const* d_in, const int* in_sizes, int n_in,
                              void* d_out, int out_size) {
    const float* h0    = (const float*)d_in[1];
    const float* c0    = (const float*)d_in[2];
    const float* embed = (const float*)d_in[5];
    const float* w_ih  = (const float*)d_in[6];
    const float* w_hh  = (const float*)d_in[7];
    const float* b_ih  = (const float*)d_in[8];
    const float* b_hh  = (const float*)d_in[9];
    const float* w_out = (const float*)d_in[10];
    const float* b_out = (const float*)d_in[11];
    float* out = (float*)d_out;

    static int attr_done = 0;
    if (!attr_done) {
        cudaFuncSetAttribute(proj_tc, cudaFuncAttributeMaxDynamicSharedMemorySize, DSMEM_P);
        cudaFuncSetAttribute(lstm_tc, cudaFuncAttributeMaxDynamicSharedMemorySize, DSMEM_L);
        attr_done = 1;
    }

    const long long BTV = (long long)B * T * V;
    long long extra = (long long)out_size - BTV;
    int mode = (extra >= (long long)(B * T)) ? 1 : 0;

    init_kernel<<<(B * H + 511) / 512, 512>>>(h0, c0, embed, out, mode);

    split_weights<<<(V * H / 4 + 255) / 256, 256>>>(w_out, 0, V * H / 4);
    split_weights<<<(G4 * H / 4 + 255) / 256, 256>>>(w_ih, 1, G4 * H / 4);
    split_weights<<<(G4 * H / 4 + 255) / 256, 256>>>(w_hh, 2, G4 * H / 4);

    long long zstart = BTV + (mode ? (long long)(B * T) : 0);
    long long zcount = (long long)out_size - zstart;
    if (zcount > 0)
        fill_zero<<<(int)((zcount + 255) / 256), 256>>>(out + zstart, (int)zcount);

    // t = 0: logits from embed[SOS]; x for step 1 stays embed[SOS] (carry)
    proj_tc<<<V / 128, 256, DSMEM_P>>>(1, out, 0, b_out);

    for (int t = 1; t < T; t++) {
        lstm_tc<<<128, 256, DSMEM_L>>>();
        lstm_act_kernel<<<(B * H) / 256, 256>>>(b_ih, b_hh);
        proj_tc<<<V / 128, 256, DSMEM_P>>>(0, out, t, b_out);
        argmax_final<<<B, 256>>>(out, embed, t, mode);
    }
}

// round 16
// speedup vs baseline: 1.1796x; 1.0519x over previous
#include <cuda_runtime.h>
#include <cuda_fp16.h>
#include <mma.h>
#include <cstdint>
#include <cfloat>

using namespace nvcuda;

#define B   64
#define H   1024
#define V   32000
#define T   40
#define G4  4096
#define SOS 1

#define KC   64
#define PE   72                     // smem pitch in half elements
#define ROWB 144                    // pitch bytes
#define NPART (V / 128)             // 250 proj blocks
#define NHH   128                   // hh partial blocks (64 mb x 2 k-halves)

// ---- BM=64 stage geometry ----
#define ARRB64 (64 * ROWB)          // 9216
#define STG64  (4 * ARRB64)         // 36864
#define DSMEM_L (2 * STG64)         // 73728  (ih kernel)

// ---- proj geometry (BM=128, 2-stage) ----
#define ARRB128 (128 * ROWB)        // 18432
#define STG128  (2 * ARRB128 + 2 * ARRB64)   // 55296
#define DSMEM_P (2 * STG128)        // 110592 (combined kernel)

// ---------------- persistent device state (device-code access ONLY) ----------
__device__ __align__(16) __half g_Wout_h[(size_t)V * H];
__device__ __align__(16) __half g_Wout_l[(size_t)V * H];
__device__ __align__(16) __half g_Wih_h[(size_t)G4 * H];
__device__ __align__(16) __half g_Wih_l[(size_t)G4 * H];
__device__ __align__(16) __half g_Whh_h[(size_t)G4 * H];
__device__ __align__(16) __half g_Whh_l[(size_t)G4 * H];
__device__ __align__(16) __half g_xh[B * H],  g_xl[B * H];
__device__ __align__(16) __half g_hh[B * H],  g_hl[B * H];
__device__ float g_c[B * H];
__device__ float g_p_ih0[B * G4];
__device__ float g_p_ih1[B * G4];
__device__ float g_p_hh0[B * G4];
__device__ float g_p_hh1[B * G4];
__device__ float g_pv[NPART * B];   // proj partial argmax values
__device__ int   g_pi[NPART * B];   // proj partial argmax indices

// ---------------- helpers ------------------------------------------------------
__device__ __forceinline__ uint32_t smem_u32(const void* p) {
    uint32_t a;
    asm("{ .reg .u64 t; cvta.to.shared.u64 t, %1; cvt.u32.u64 %0, t; }"
        : "=r"(a) : "l"(p));
    return a;
}
__device__ __forceinline__ void cp16(uint32_t s, const void* g) {
    asm volatile("cp.async.cg.shared.global [%0], [%1], 16;" :: "r"(s), "l"(g));
}
__device__ __forceinline__ void cp_commit() {
    asm volatile("cp.async.commit_group;" ::: "memory");
}
__device__ __forceinline__ void cp_wait1() {
    asm volatile("cp.async.wait_group 1;" ::: "memory");
}
__device__ __forceinline__ void cp_wait0() {
    asm volatile("cp.async.wait_group 0;" ::: "memory");
}
__device__ __forceinline__ void split_pair(float x, __half& hi, __half& lo) {
    hi = __float2half_rn(x);
    lo = __float2half_rn(x - __half2float(hi));
}

// ---------------- BM=64 GEMM mainloop (2-stage, parameterized K window) --------
// D[64 rows of A (m0..), 64 batch] over K in [kOff, kOff + nst*KC)
__device__ __forceinline__ void gemm64(
    const __half* __restrict__ Ah, const __half* __restrict__ Al,
    const __half* __restrict__ Bh, const __half* __restrict__ Bl,
    int m0, int kOff, int nst, char* sm, float* sC, __half* sCh)
{
    const int tid = threadIdx.x;
    const int wid = tid >> 5;
    const int ms = (wid & 3) * 16;
    const int nb = (wid >> 2) * 32;
    const uint32_t sbase = smem_u32(sm);

    const int r0 = tid >> 3,         c0 = tid & 7;
    const int r1 = (tid + 256) >> 3, c1 = tid & 7;
    const uint32_t so0 = (uint32_t)(r0 * ROWB + c0 * 16);
    const uint32_t so1 = (uint32_t)(r1 * ROWB + c1 * 16);

    wmma::fragment<wmma::accumulator, 16, 16, 16, float> fC[2];
    wmma::fragment<wmma::accumulator, 16, 16, 16, __half> fE[2];
    wmma::fill_fragment(fC[0], 0.0f);
    wmma::fill_fragment(fC[1], 0.0f);
    wmma::fill_fragment(fE[0], __float2half(0.0f));
    wmma::fill_fragment(fE[1], __float2half(0.0f));

#pragma unroll
    for (int s = 0; s < 2; s++) {
        const int kt = kOff + s * KC;
        const uint32_t sb = sbase + (uint32_t)s * STG64;
        const size_t ga0 = (size_t)(m0 + r0) * H + kt + c0 * 8;
        const size_t ga1 = (size_t)(m0 + r1) * H + kt + c1 * 8;
        const size_t gb0 = (size_t)r0 * H + kt + c0 * 8;
        const size_t gb1 = (size_t)r1 * H + kt + c1 * 8;
        cp16(sb + 0 * ARRB64 + so0, Ah + ga0);  cp16(sb + 0 * ARRB64 + so1, Ah + ga1);
        cp16(sb + 1 * ARRB64 + so0, Al + ga0);  cp16(sb + 1 * ARRB64 + so1, Al + ga1);
        cp16(sb + 2 * ARRB64 + so0, Bh + gb0);  cp16(sb + 2 * ARRB64 + so1, Bh + gb1);
        cp16(sb + 3 * ARRB64 + so0, Bl + gb0);  cp16(sb + 3 * ARRB64 + so1, Bl + gb1);
        cp_commit();
    }

    for (int s = 0; s < nst; s++) {
        if (s < nst - 1) cp_wait1(); else cp_wait0();
        __syncthreads();

        const __half* st =
            reinterpret_cast<const __half*>(sm + (size_t)(s & 1) * STG64);
        const __half* sAh = st;
        const __half* sAl = st + ARRB64 / 2;
        const __half* sBh = st + 2 * (ARRB64 / 2);
        const __half* sBl = st + 3 * (ARRB64 / 2);

#pragma unroll
        for (int ks = 0; ks < KC; ks += 16) {
            wmma::fragment<wmma::matrix_a, 16, 16, 16, __half,
                           wmma::row_major> fAh, fAl;
            wmma::load_matrix_sync(fAh, sAh + ms * PE + ks, PE);
            wmma::load_matrix_sync(fAl, sAl + ms * PE + ks, PE);
#pragma unroll
            for (int j = 0; j < 2; j++) {
                wmma::fragment<wmma::matrix_b, 16, 16, 16, __half,
                               wmma::col_major> fBh, fBl;
                const int nr = nb + j * 16;
                wmma::load_matrix_sync(fBh, sBh + nr * PE + ks, PE);
                wmma::load_matrix_sync(fBl, sBl + nr * PE + ks, PE);
                wmma::mma_sync(fC[j], fAh, fBh, fC[j]);
                wmma::mma_sync(fE[j], fAh, fBl, fE[j]);
                wmma::mma_sync(fE[j], fAl, fBh, fE[j]);
            }
        }
        __syncthreads();

        if (s + 2 < nst) {
            const int kt = kOff + (s + 2) * KC;
            const uint32_t sb = sbase + (uint32_t)(s & 1) * STG64;
            const size_t ga0 = (size_t)(m0 + r0) * H + kt + c0 * 8;
            const size_t ga1 = (size_t)(m0 + r1) * H + kt + c1 * 8;
            const size_t gb0 = (size_t)r0 * H + kt + c0 * 8;
            const size_t gb1 = (size_t)r1 * H + kt + c1 * 8;
            cp16(sb + 0 * ARRB64 + so0, Ah + ga0);  cp16(sb + 0 * ARRB64 + so1, Ah + ga1);
            cp16(sb + 1 * ARRB64 + so0, Al + ga0);  cp16(sb + 1 * ARRB64 + so1, Al + ga1);
            cp16(sb + 2 * ARRB64 + so0, Bh + gb0);  cp16(sb + 2 * ARRB64 + so1, Bh + gb1);
            cp16(sb + 3 * ARRB64 + so0, Bl + gb0);  cp16(sb + 3 * ARRB64 + so1, Bl + gb1);
            cp_commit();
        }
    }

    wmma::store_matrix_sync(sC + ms * 68 + nb,       fC[0], 68, wmma::mem_row_major);
    wmma::store_matrix_sync(sC + ms * 68 + nb + 16,  fC[1], 68, wmma::mem_row_major);
    wmma::store_matrix_sync(sCh + ms * 72 + nb,      fE[0], 72, wmma::mem_row_major);
    wmma::store_matrix_sync(sCh + ms * 72 + nb + 16, fE[1], 72, wmma::mem_row_major);
    __syncthreads();
}

// ---------------- proj GEMM mainloop (BM=128; round-11 verbatim) ---------------
__device__ __forceinline__ void gemm128(
    const __half* __restrict__ Ah, const __half* __restrict__ Al,
    const __half* __restrict__ Bh, const __half* __restrict__ Bl,
    int m0, char* sm, float* sC, __half* sCh)
{
    const int tid = threadIdx.x;
    const int wid = tid >> 5;
    const int ms = (wid & 3) * 32;
    const int nb = (wid >> 2) * 32;
    const uint32_t sbase = smem_u32(sm);

    const int c0 = tid & 7;
    const uint32_t soA[4] = {
        (uint32_t)(((tid + 0)   >> 3) * ROWB + c0 * 16),
        (uint32_t)(((tid + 256) >> 3) * ROWB + c0 * 16),
        (uint32_t)(((tid + 512) >> 3) * ROWB + c0 * 16),
        (uint32_t)(((tid + 768) >> 3) * ROWB + c0 * 16)
    };
    const int rA[4] = { (tid + 0) >> 3, (tid + 256) >> 3,
                        (tid + 512) >> 3, (tid + 768) >> 3 };

    wmma::fragment<wmma::accumulator, 16, 16, 16, float> fC[2][2];
    wmma::fragment<wmma::accumulator, 16, 16, 16, __half> fE[2][2];
#pragma unroll
    for (int i = 0; i < 2; i++)
#pragma unroll
        for (int j = 0; j < 2; j++) {
            wmma::fill_fragment(fC[i][j], 0.0f);
            wmma::fill_fragment(fE[i][j], __float2half(0.0f));
        }

#pragma unroll
    for (int s = 0; s < 2; s++) {
        const int kt = s * KC;
        const uint32_t sb = sbase + (uint32_t)s * STG128;
#pragma unroll
        for (int v = 0; v < 4; v++) {
            const size_t ga = (size_t)(m0 + rA[v]) * H + kt + c0 * 8;
            cp16(sb + 0 * ARRB128 + soA[v], Ah + ga);
            cp16(sb + 1 * ARRB128 + soA[v], Al + ga);
        }
#pragma unroll
        for (int v = 0; v < 2; v++) {
            const size_t gb = (size_t)rA[v] * H + kt + c0 * 8;
            cp16(sb + 2 * ARRB128 + soA[v], Bh + gb);
            cp16(sb + 2 * ARRB128 + ARRB64 + soA[v], Bl + gb);
        }
        cp_commit();
    }

    const int NSTP = H / KC;
    for (int s = 0; s < NSTP; s++) {
        if (s < NSTP - 1) cp_wait1(); else cp_wait0();
        __syncthreads();

        const __half* st =
            reinterpret_cast<const __half*>(sm + (size_t)(s & 1) * STG128);
        const __half* sAh = st;
        const __half* sAl = st + ARRB128 / 2;
        const __half* sBh = st + 2 * (ARRB128 / 2);
        const __half* sBl = st + 2 * (ARRB128 / 2) + ARRB64 / 2;

#pragma unroll
        for (int ks = 0; ks < KC; ks += 16) {
            wmma::fragment<wmma::matrix_a, 16, 16, 16, __half,
                           wmma::row_major> fAh[2], fAl[2];
#pragma unroll
            for (int i = 0; i < 2; i++) {
                wmma::load_matrix_sync(fAh[i], sAh + (ms + i * 16) * PE + ks, PE);
                wmma::load_matrix_sync(fAl[i], sAl + (ms + i * 16) * PE + ks, PE);
            }
#pragma unroll
            for (int j = 0; j < 2; j++) {
                wmma::fragment<wmma::matrix_b, 16, 16, 16, __half,
                               wmma::col_major> fBh, fBl;
                const int nr = nb + j * 16;
                wmma::load_matrix_sync(fBh, sBh + nr * PE + ks, PE);
                wmma::load_matrix_sync(fBl, sBl + nr * PE + ks, PE);
#pragma unroll
                for (int i = 0; i < 2; i++) {
                    wmma::mma_sync(fC[i][j], fAh[i], fBh, fC[i][j]);
                    wmma::mma_sync(fE[i][j], fAh[i], fBl, fE[i][j]);
                    wmma::mma_sync(fE[i][j], fAl[i], fBh, fE[i][j]);
                }
            }
        }
        __syncthreads();

        if (s + 2 < NSTP) {
            const int kt = (s + 2) * KC;
            const uint32_t sb = sbase + (uint32_t)(s & 1) * STG128;
#pragma unroll
            for (int v = 0; v < 4; v++) {
                const size_t ga = (size_t)(m0 + rA[v]) * H + kt + c0 * 8;
                cp16(sb + 0 * ARRB128 + soA[v], Ah + ga);
                cp16(sb + 1 * ARRB128 + soA[v], Al + ga);
            }
#pragma unroll
            for (int v = 0; v < 2; v++) {
                const size_t gb = (size_t)rA[v] * H + kt + c0 * 8;
                cp16(sb + 2 * ARRB128 + soA[v], Bh + gb);
                cp16(sb + 2 * ARRB128 + ARRB64 + soA[v], Bl + gb);
            }
            cp_commit();
        }
    }

#pragma unroll
    for (int i = 0; i < 2; i++)
#pragma unroll
        for (int j = 0; j < 2; j++) {
            wmma::store_matrix_sync(sC + (ms + i * 16) * 68 + nb + j * 16,
                                    fC[i][j], 68, wmma::mem_row_major);
            wmma::store_matrix_sync(sCh + (ms + i * 16) * 72 + nb + j * 16,
                                    fE[i][j], 72, wmma::mem_row_major);
        }
    __syncthreads();
}

// ---------------- combined kernel: proj(t) + w_hh partial for step t+1 ---------
// bid < NPART : proj path (uses h(t), or x0 at t=0) + partial argmax (r11 style)
// bid >= NPART: hh partial path (uses h(t)), k-split x2; skipped if !do_hh
__global__ __launch_bounds__(256, 2)
void proj_hh_tc(int useX0, float* __restrict__ dst, int t,
                const float* __restrict__ bias, int do_hh)
{
    extern __shared__ char sm[];
    const int tid = threadIdx.x;

    if (blockIdx.x >= NPART) {
        if (!do_hh) return;
        float* sC  = reinterpret_cast<float*>(sm);
        __half* sCh = reinterpret_cast<__half*>(sm + 64 * 68 * 4);
        const int lb = blockIdx.x - NPART;
        const int mb = lb & 63;
        const int kh = lb >> 6;
        gemm64(g_Whh_h, g_Whh_l, g_hh, g_hl, mb * 64, kh * 512, 8, sm, sC, sCh);
        float* gp = kh ? g_p_hh1 : g_p_hh0;
        const int ml = tid & 63;
        const int nlb = tid >> 6;
        const int gm = mb * 64 + ml;
#pragma unroll
        for (int r = 0; r < 16; r++) {
            const int n = nlb + r * 4;
            gp[(size_t)n * G4 + gm] = sC[ml * 68 + n] + __half2float(sCh[ml * 72 + n]);
        }
        return;
    }

    // ---- proj path ----
    float* sC  = reinterpret_cast<float*>(sm);
    __half* sCh = reinterpret_cast<__half*>(sm + 128 * 68 * 4);
    __shared__ float sBias[128];
    __shared__ float sPV[256];
    __shared__ int   sPI[256];

    const int m0 = blockIdx.x * 128;
    if (tid < 128) sBias[tid] = bias[m0 + tid];

    const __half* Bh = useX0 ? g_xh : g_hh;
    const __half* Bl = useX0 ? g_xl : g_hl;
    gemm128(g_Wout_h, g_Wout_l, Bh, Bl, m0, sm, sC, sCh);

    const int ml = tid & 127;
    const int nlb = tid >> 7;
    const int gm = m0 + ml;
    const float bb = sBias[ml];
#pragma unroll
    for (int r = 0; r < 32; r++) {
        const int n = nlb + r * 2;
        dst[((size_t)n * T + t) * (size_t)V + gm] =
            sC[ml * 68 + n] + __half2float(sCh[ml * 72 + n]) + bb;
    }

    const int n = tid & 63, q = tid >> 6;
    float bv = -FLT_MAX;
    int bi = 0;
    for (int r = q * 32; r < q * 32 + 32; r++) {
        float v = sC[r * 68 + n] + __half2float(sCh[r * 72 + n]) + sBias[r];
        if (v > bv) { bv = v; bi = m0 + r; }
    }
    sPV[tid] = bv;
    sPI[tid] = bi;
    __syncthreads();
    if (tid < 64) {
        float v0 = sPV[tid];
        int   i0 = sPI[tid];
#pragma unroll
        for (int qq = 1; qq < 4; qq++) {
            float v = sPV[tid + qq * 64];
            int   i = sPI[tid + qq * 64];
            if (v > v0 || (v == v0 && i < i0)) { v0 = v; i0 = i; }
        }
        g_pv[blockIdx.x * B + tid] = v0;
        g_pi[blockIdx.x * B + tid] = i0;
    }
}

// ---------------- w_ih * x partial kernel (k-split x2, 128 blocks) -------------
__global__ __launch_bounds__(256, 2)
void lstm_ih_tc()
{
    extern __shared__ char sm[];
    float* sC  = reinterpret_cast<float*>(sm);
    __half* sCh = reinterpret_cast<__half*>(sm + 64 * 68 * 4);
    const int mb = blockIdx.x & 63;
    const int kh = blockIdx.x >> 6;

    gemm64(g_Wih_h, g_Wih_l, g_xh, g_xl, mb * 64, kh * 512, 8, sm, sC, sCh);

    float* gp = kh ? g_p_ih1 : g_p_ih0;
    const int ml = threadIdx.x & 63;
    const int nlb = threadIdx.x >> 6;
    const int gm = mb * 64 + ml;
#pragma unroll
    for (int r = 0; r < 16; r++) {
        const int n = nlb + r * 4;
        gp[(size_t)n * G4 + gm] = sC[ml * 68 + n] + __half2float(sCh[ml * 72 + n]);
    }
}

// ---------------- weight pre-split ---------------------------------------------
__global__ void split_weights(const float* __restrict__ src, int which, int n4) {
    int i4 = blockIdx.x * blockDim.x + threadIdx.x;
    if (i4 >= n4) return;
    __half* dh;
    __half* dl;
    if (which == 0)      { dh = g_Wout_h; dl = g_Wout_l; }
    else if (which == 1) { dh = g_Wih_h;  dl = g_Wih_l; }
    else                 { dh = g_Whh_h;  dl = g_Whh_l; }
    float4 v = reinterpret_cast<const float4*>(src)[i4];
    __half h0, l0, h1, l1, h2, l2, h3, l3;
    split_pair(v.x, h0, l0);
    split_pair(v.y, h1, l1);
    split_pair(v.z, h2, l2);
    split_pair(v.w, h3, l3);
    size_t o = (size_t)i4 * 4;
    dh[o] = h0; dh[o + 1] = h1; dh[o + 2] = h2; dh[o + 3] = h3;
    dl[o] = l0; dl[o + 1] = l1; dl[o + 2] = l2; dl[o + 3] = l3;
}

// ---------------- small kernels --------------------------------------------------
__global__ void init_kernel(const float* __restrict__ h0,
                            const float* __restrict__ c0,
                            const float* __restrict__ embed,
                            float* __restrict__ out, int mode) {
    int idx = blockIdx.x * blockDim.x + threadIdx.x;
    if (idx < B * H) {
        g_c[idx] = c0[idx];
        __half hi, lo;
        split_pair(h0[idx], hi, lo);
        g_hh[idx] = hi;
        g_hl[idx] = lo;
        split_pair(embed[(size_t)SOS * H + (idx & (H - 1))], hi, lo);
        g_xh[idx] = hi;
        g_xl[idx] = lo;
    }
    if (idx < B && mode)
        out[(size_t)B * T * V + (size_t)idx * T + 0] = (float)SOS;
}

__global__ void fill_zero(float* __restrict__ p, int n) {
    int i = blockIdx.x * blockDim.x + threadIdx.x;
    if (i < n) p[i] = 0.0f;
}

__global__ void lstm_act_kernel(const float* __restrict__ b_ih,
                                const float* __restrict__ b_hh) {
    int idx = blockIdx.x * blockDim.x + threadIdx.x;   // B*H
    int b = idx >> 10;
    int j = idx & (H - 1);
    const size_t base = (size_t)b * G4;
    float gi = g_p_ih0[base + j]        + g_p_ih1[base + j]
             + g_p_hh0[base + j]        + g_p_hh1[base + j]
             + b_ih[j]        + b_hh[j];
    float gf = g_p_ih0[base + j + 1024] + g_p_ih1[base + j + 1024]
             + g_p_hh0[base + j + 1024] + g_p_hh1[base + j + 1024]
             + b_ih[j + 1024] + b_hh[j + 1024];
    float gg = g_p_ih0[base + j + 2048] + g_p_ih1[base + j + 2048]
             + g_p_hh0[base + j + 2048] + g_p_hh1[base + j + 2048]
             + b_ih[j + 2048] + b_hh[j + 2048];
    float go = g_p_ih0[base + j + 3072] + g_p_ih1[base + j + 3072]
             + g_p_hh0[base + j + 3072] + g_p_hh1[base + j + 3072]
             + b_ih[j + 3072] + b_hh[j + 3072];
    float c  = g_c[idx];
    float si = 1.0f / (1.0f + expf(-gi));
    float sf = 1.0f / (1.0f + expf(-gf));
    float so = 1.0f / (1.0f + expf(-go));
    float c2 = sf * c + si * tanhf(gg);
    float h2 = so * tanhf(c2);
    g_c[idx] = c2;
    __half hi, lo;
    split_pair(h2, hi, lo);
    g_hh[idx] = hi;
    g_hl[idx] = lo;
}

// final argmax over proj partials + fused embed gather/split for next step
__global__ void argmax_final(float* __restrict__ out,
                             const float* __restrict__ embed,
                             int t, int mode) {
    const int b = blockIdx.x;
    const int tid = threadIdx.x;
    float bv = -FLT_MAX;
    int bi = 0x7fffffff;
    for (int i = tid; i < NPART; i += 256) {
        float v = g_pv[i * B + b];
        int   ix = g_pi[i * B + b];
        if (v > bv || (v == bv && ix < bi)) { bv = v; bi = ix; }
    }
    __shared__ float sv[256];
    __shared__ int   si[256];
    sv[tid] = bv;
    si[tid] = bi;
    __syncthreads();
    for (int s = 128; s > 0; s >>= 1) {
        if (tid < s) {
            float ov = sv[tid + s];
            int   oi = si[tid + s];
            if (ov > sv[tid] || (ov == sv[tid] && oi < si[tid])) {
                sv[tid] = ov;
                si[tid] = oi;
            }
        }
        __syncthreads();
    }
    const int sym = si[0];
    if (tid == 0 && mode)
        out[(size_t)B * T * V + (size_t)b * T + t] = (float)sym;
    const float4* erow = reinterpret_cast<const float4*>(embed + (size_t)sym * H);
    float4 v = erow[tid];
    int j = tid * 4;
    __half hi, lo;
    split_pair(v.x, hi, lo); g_xh[b * H + j]     = hi; g_xl[b * H + j]     = lo;
    split_pair(v.y, hi, lo); g_xh[b * H + j + 1] = hi; g_xl[b * H + j + 1] = lo;
    split_pair(v.z, hi, lo); g_xh[b * H + j + 2] = hi; g_xl[b * H + j + 2] = lo;
    split_pair(v.w, hi, lo); g_xh[b * H + j + 3] = hi; g_xl[b * H + j + 3] = lo;
}

// ---------------- launch ----------------------------------------------------------
extern "C" void kernel_launch(void* const* d_in, const int* in_sizes, int n_in,
                              void* d_out, int out_size) {
    const float* h0    = (const float*)d_in[1];
    const float* c0    = (const float*)d_in[2];
    const float* embed = (const float*)d_in[5];
    const float* w_ih  = (const float*)d_in[6];
    const float* w_hh  = (const float*)d_in[7];
    const float* b_ih  = (const float*)d_in[8];
    const float* b_hh  = (const float*)d_in[9];
    const float* w_out = (const float*)d_in[10];
    const float* b_out = (const float*)d_in[11];
    float* out = (float*)d_out;

    static int attr_done = 0;
    if (!attr_done) {
        cudaFuncSetAttribute(proj_hh_tc, cudaFuncAttributeMaxDynamicSharedMemorySize, DSMEM_P);
        cudaFuncSetAttribute(lstm_ih_tc, cudaFuncAttributeMaxDynamicSharedMemorySize, DSMEM_L);
        attr_done = 1;
    }

    const long long BTV = (long long)B * T * V;
    long long extra = (long long)out_size - BTV;
    int mode = (extra >= (long long)(B * T)) ? 1 : 0;

    init_kernel<<<(B * H + 511) / 512, 512>>>(h0, c0, embed, out, mode);

    split_weights<<<(V * H / 4 + 255) / 256, 256>>>(w_out, 0, V * H / 4);
    split_weights<<<(G4 * H / 4 + 255) / 256, 256>>>(w_ih, 1, G4 * H / 4);
    split_weights<<<(G4 * H / 4 + 255) / 256, 256>>>(w_hh, 2, G4 * H / 4);

    long long zstart = BTV + (mode ? (long long)(B * T) : 0);
    long long zcount = (long long)out_size - zstart;
    if (zcount > 0)
        fill_zero<<<(int)((zcount + 255) / 256), 256>>>(out + zstart, (int)zcount);

    // t = 0: proj(embed[SOS]) + hh partial for step 1 (uses h0).
    // No argmax on proj(0): step 1's x stays embed[SOS] (carry semantics).
    proj_hh_tc<<<NPART + NHH, 256, DSMEM_P>>>(1, out, 0, b_out, 1);

    for (int t = 1; t < T; t++) {
        lstm_ih_tc<<<NHH, 256, DSMEM_L>>>();         // w_ih * x(t)
        lstm_act_kernel<<<(B * H) / 256, 256>>>(b_ih, b_hh);  // -> h(t), c(t)
        // proj(t) with h(t) + hh partial for step t+1 (skip at t = T-1)
        proj_hh_tc<<<NPART + NHH, 256, DSMEM_P>>>(0, out, t, b_out, t < T - 1);
        argmax_final<<<B, 256>>>(out, embed, t, mode);  // sym(t), x(t+1)
    }
}